// round 1
// baseline (speedup 1.0000x reference)
#include <cuda_runtime.h>
#include <math.h>

#define B 4
#define N 2048
#define D 256
#define KS 16

// ---------------- scratch (device globals: allocation-free) ----------------
__device__ float g_xT[B * D * N];   // src transposed [B][D][N]
__device__ float g_q [B * D * N];
__device__ float g_k [B * D * N];
__device__ float g_v [B * D * N];
__device__ float g_S [(size_t)B * N * N]; // scores -> attn (in place)
__device__ float g_x1[B * N * D];   // attn @ v  (row-major [n][d]); reused for m3
__device__ float g_h [B * N * D];
__device__ float g_m1[B * N * D];
__device__ float g_m2[B * N * D];

// ---------------- 1. transpose src [B,N,D] -> xT [B,D,N] ----------------
__global__ __launch_bounds__(256) void transpose_kernel(const float* __restrict__ src) {
    __shared__ float tile[32][33];
    int b  = blockIdx.z;
    int n0 = blockIdx.x * 32;
    int c0 = blockIdx.y * 32;
    int tx = threadIdx.x, ty = threadIdx.y; // (32, 8)
#pragma unroll
    for (int i = 0; i < 4; i++)
        tile[ty + i * 8][tx] = src[((size_t)(b * N + n0 + ty + i * 8)) * D + c0 + tx];
    __syncthreads();
#pragma unroll
    for (int i = 0; i < 4; i++)
        g_xT[((size_t)(b * D + c0 + ty + i * 8)) * N + n0 + tx] = tile[tx][ty + i * 8];
}

// ---------------- 2. fused QKV conv1d (K=16, SAME pad: low=7, high=8) ----------------
// q[b,o,n] = bq[o] + sum_c sum_k Wq[o,c,k] * x[b,c,n-7+k]
// Block: 64(o) x 64(n) tile, computes q,k,v together (x tile reused 3x).
__global__ __launch_bounds__(256) void conv_qkv_kernel(
    const float* __restrict__ Wq, const float* __restrict__ Wk, const float* __restrict__ Wv,
    const float* __restrict__ bq, const float* __restrict__ bk, const float* __restrict__ bv)
{
    __shared__ float ws[3][KS][68]; // [mat][k][o], padded
    __shared__ float xs[80];        // n0-7 .. n0+72
    int b  = blockIdx.z;
    int o0 = blockIdx.y * 64;
    int n0 = blockIdx.x * 64;
    int t  = threadIdx.x;
    int tx = t & 15, ty = t >> 4;   // tx -> n (fast), ty -> o

    float accq[4][4] = {}, acck[4][4] = {}, accv[4][4] = {};
    const float* Wm[3] = {Wq, Wk, Wv};

    for (int c = 0; c < D; c++) {
        if (t < 80) {
            int n = n0 - 7 + t;
            xs[t] = (n >= 0 && n < N) ? g_xT[(size_t)(b * D + c) * N + n] : 0.f;
        }
#pragma unroll
        for (int m = 0; m < 3; m++) {
            const float* W = Wm[m];
#pragma unroll
            for (int r = 0; r < 4; r++) {
                int idx = t + r * 256;          // 0..1023
                int o = idx >> 4, k = idx & 15;
                ws[m][k][o] = W[((size_t)(o0 + o) * D + c) * KS + k];
            }
        }
        __syncthreads();
#pragma unroll
        for (int k = 0; k < KS; k++) {
            float4 wq4 = *(const float4*)&ws[0][k][ty * 4];
            float4 wk4 = *(const float4*)&ws[1][k][ty * 4];
            float4 wv4 = *(const float4*)&ws[2][k][ty * 4];
            float wqa[4] = {wq4.x, wq4.y, wq4.z, wq4.w};
            float wka[4] = {wk4.x, wk4.y, wk4.z, wk4.w};
            float wva[4] = {wv4.x, wv4.y, wv4.z, wv4.w};
            float xa[4];
#pragma unroll
            for (int j = 0; j < 4; j++) xa[j] = xs[tx * 4 + j + k];
#pragma unroll
            for (int i = 0; i < 4; i++)
#pragma unroll
                for (int j = 0; j < 4; j++) {
                    accq[i][j] = fmaf(wqa[i], xa[j], accq[i][j]);
                    acck[i][j] = fmaf(wka[i], xa[j], acck[i][j]);
                    accv[i][j] = fmaf(wva[i], xa[j], accv[i][j]);
                }
        }
        __syncthreads();
    }
#pragma unroll
    for (int i = 0; i < 4; i++) {
        int o = o0 + ty * 4 + i;
        float bqv = bq[o], bkv = bk[o], bvv = bv[o];
        size_t base = (size_t)(b * D + o) * N + n0 + tx * 4;
        float4 q4, k4, v4;
        float* qp = (float*)&q4; float* kp = (float*)&k4; float* vp = (float*)&v4;
#pragma unroll
        for (int j = 0; j < 4; j++) {
            qp[j] = accq[i][j] + bqv;
            kp[j] = acck[i][j] + bkv;
            vp[j] = accv[i][j] + bvv;
        }
        *(float4*)&g_q[base] = q4;
        *(float4*)&g_k[base] = k4;
        *(float4*)&g_v[base] = v4;
    }
}

// ---------------- 3. scores = qT k * scale - dis, masked by adj ----------------
__global__ __launch_bounds__(256) void scores_kernel(const float* __restrict__ dis,
                                                     const int* __restrict__ adj)
{
    __shared__ float qs[4][64];
    __shared__ float ks[4][64];
    int b  = blockIdx.z;
    int n0 = blockIdx.y * 64;
    int m0 = blockIdx.x * 64;
    int t  = threadIdx.x;
    int tx = t & 15, ty = t >> 4;  // tx -> m (fast), ty -> n
    float acc[4][4] = {};          // [n_i][m_j]

    for (int c0 = 0; c0 < D; c0 += 4) {
        int cc = t >> 6, col = t & 63;
        qs[cc][col] = g_q[(size_t)(b * D + c0 + cc) * N + n0 + col];
        ks[cc][col] = g_k[(size_t)(b * D + c0 + cc) * N + m0 + col];
        __syncthreads();
#pragma unroll
        for (int c = 0; c < 4; c++) {
            float4 q4 = *(const float4*)&qs[c][ty * 4];
            float4 k4 = *(const float4*)&ks[c][tx * 4];
            float qa[4] = {q4.x, q4.y, q4.z, q4.w};
            float ka[4] = {k4.x, k4.y, k4.z, k4.w};
#pragma unroll
            for (int i = 0; i < 4; i++)
#pragma unroll
                for (int j = 0; j < 4; j++)
                    acc[i][j] = fmaf(qa[i], ka[j], acc[i][j]);
        }
        __syncthreads();
    }
    const float scale = 0.0625f; // 1/sqrt(256)
#pragma unroll
    for (int i = 0; i < 4; i++) {
        int n = n0 + ty * 4 + i;
        size_t base = ((size_t)b * N + n) * N + m0 + tx * 4;
        float4 d4 = *(const float4*)&dis[base];
        int4   a4 = *(const int4*)&adj[base];
        float4 s;
        s.x = (a4.x > 0) ? acc[i][0] * scale - d4.x : -1e9f;
        s.y = (a4.y > 0) ? acc[i][1] * scale - d4.y : -1e9f;
        s.z = (a4.z > 0) ? acc[i][2] * scale - d4.z : -1e9f;
        s.w = (a4.w > 0) ? acc[i][3] * scale - d4.w : -1e9f;
        *(float4*)&g_S[base] = s;
    }
}

// ---------------- 4. row softmax; attn -> g_S (in place); out_attn = x_lst + attn ----------------
__global__ __launch_bounds__(256) void softmax_kernel(const float* __restrict__ xlst,
                                                      float* __restrict__ out_attn)
{
    __shared__ float row[N];
    __shared__ float red[256];
    int r = blockIdx.x;          // b*N + n
    int t = threadIdx.x;
    size_t base = (size_t)r * N;

    float lmax = -1e30f;
    for (int j = t; j < N; j += 256) { float v = g_S[base + j]; row[j] = v; lmax = fmaxf(lmax, v); }
    red[t] = lmax; __syncthreads();
    for (int s = 128; s > 0; s >>= 1) { if (t < s) red[t] = fmaxf(red[t], red[t + s]); __syncthreads(); }
    float mx = red[0];
    __syncthreads();

    float lsum = 0.f;
    for (int j = t; j < N; j += 256) { float e = expf(row[j] - mx); row[j] = e; lsum += e; }
    red[t] = lsum; __syncthreads();
    for (int s = 128; s > 0; s >>= 1) { if (t < s) red[t] += red[t + s]; __syncthreads(); }
    float inv = 1.f / red[0];

    for (int j = t; j < N; j += 256) {
        float a = row[j] * inv;
        g_S[base + j] = a;
        out_attn[base + j] = xlst[base + j] + a;
    }
}

// ---------------- 5. x1[b,n,c] = sum_m attn[n,m] * v[c,m] ----------------
__global__ __launch_bounds__(256) void av_kernel() {
    __shared__ float As[64][20];
    __shared__ float Vs[64][20];
    int b  = blockIdx.z;
    int n0 = blockIdx.y * 64;
    int c0 = blockIdx.x * 64;
    int t  = threadIdx.x;
    int tx = t & 15, ty = t >> 4;  // tx -> c (fast), ty -> n
    float acc[4][4] = {};          // [n_i][c_j]

    int row = t >> 2, seg = t & 3;
    for (int mm = 0; mm < N; mm += 16) {
        *(float4*)&As[row][seg * 4] = *(const float4*)&g_S[((size_t)b * N + n0 + row) * N + mm + seg * 4];
        *(float4*)&Vs[row][seg * 4] = *(const float4*)&g_v[((size_t)b * D + c0 + row) * N + mm + seg * 4];
        __syncthreads();
#pragma unroll
        for (int jg = 0; jg < 4; jg++) {
            float4 a4[4], v4[4];
#pragma unroll
            for (int i = 0; i < 4; i++) a4[i] = *(const float4*)&As[ty * 4 + i][jg * 4];
#pragma unroll
            for (int j = 0; j < 4; j++) v4[j] = *(const float4*)&Vs[tx * 4 + j][jg * 4];
#pragma unroll
            for (int i = 0; i < 4; i++)
#pragma unroll
                for (int j = 0; j < 4; j++)
                    acc[i][j] += a4[i].x * v4[j].x + a4[i].y * v4[j].y
                               + a4[i].z * v4[j].z + a4[i].w * v4[j].w;
        }
        __syncthreads();
    }
#pragma unroll
    for (int i = 0; i < 4; i++) {
        size_t base = ((size_t)b * N + n0 + ty * 4 + i) * D + c0 + tx * 4;
        float4 y = {acc[i][0], acc[i][1], acc[i][2], acc[i][3]};
        *(float4*)&g_x1[base] = y;
    }
}

// ---------------- 6. out = LayerNorm(A + Bsrc) * g + be ----------------
__global__ __launch_bounds__(256) void add_ln_kernel(const float* __restrict__ A,
                                                     const float* __restrict__ Bsrc,
                                                     const float* __restrict__ g,
                                                     const float* __restrict__ be,
                                                     float* __restrict__ outp)
{
    __shared__ float red[256];
    int r = blockIdx.x, t = threadIdx.x;
    size_t base = (size_t)r * D;
    float x = A[base + t] + Bsrc[base + t];
    red[t] = x; __syncthreads();
    for (int s = 128; s > 0; s >>= 1) { if (t < s) red[t] += red[t + s]; __syncthreads(); }
    float mu = red[0] * (1.f / D);
    __syncthreads();
    float dv = x - mu;
    red[t] = dv * dv; __syncthreads();
    for (int s = 128; s > 0; s >>= 1) { if (t < s) red[t] += red[t + s]; __syncthreads(); }
    float var = red[0] * (1.f / D);
    outp[base + t] = dv * rsqrtf(var + 1e-5f) * g[t] + be[t];
}

// ---------------- 7. Y[n,o] = act(sum_c X[n,c] * W[o,c] + b[o]) ----------------
__global__ __launch_bounds__(256) void mlp_kernel(const float* __restrict__ X,
                                                  const float* __restrict__ W,
                                                  const float* __restrict__ bias,
                                                  float* __restrict__ Y, int leaky)
{
    __shared__ float Xs[64][20];
    __shared__ float Ws[64][20];
    int r0 = blockIdx.y * 64;  // over B*N rows
    int o0 = blockIdx.x * 64;
    int t  = threadIdx.x;
    int tx = t & 15, ty = t >> 4;  // tx -> o (fast), ty -> n
    float acc[4][4] = {};

    int row = t >> 2, seg = t & 3;
    for (int cc = 0; cc < D; cc += 16) {
        *(float4*)&Xs[row][seg * 4] = *(const float4*)&X[(size_t)(r0 + row) * D + cc + seg * 4];
        *(float4*)&Ws[row][seg * 4] = *(const float4*)&W[(size_t)(o0 + row) * D + cc + seg * 4];
        __syncthreads();
#pragma unroll
        for (int jg = 0; jg < 4; jg++) {
            float4 x4[4], w4[4];
#pragma unroll
            for (int i = 0; i < 4; i++) x4[i] = *(const float4*)&Xs[ty * 4 + i][jg * 4];
#pragma unroll
            for (int j = 0; j < 4; j++) w4[j] = *(const float4*)&Ws[tx * 4 + j][jg * 4];
#pragma unroll
            for (int i = 0; i < 4; i++)
#pragma unroll
                for (int j = 0; j < 4; j++)
                    acc[i][j] += x4[i].x * w4[j].x + x4[i].y * w4[j].y
                               + x4[i].z * w4[j].z + x4[i].w * w4[j].w;
        }
        __syncthreads();
    }
    float4 b4 = *(const float4*)&bias[o0 + tx * 4];
    float ba[4] = {b4.x, b4.y, b4.z, b4.w};
#pragma unroll
    for (int i = 0; i < 4; i++) {
        float4 y;
        float* yp = (float*)&y;
#pragma unroll
        for (int j = 0; j < 4; j++) {
            float v = acc[i][j] + ba[j];
            if (leaky) v = (v > 0.f) ? v : 0.01f * v;
            yp[j] = v;
        }
        *(float4*)&Y[(size_t)(r0 + ty * 4 + i) * D + o0 + tx * 4] = y;
    }
}

// ---------------- launch ----------------
extern "C" void kernel_launch(void* const* d_in, const int* in_sizes, int n_in,
                              void* d_out, int out_size) {
    const float* src  = (const float*)d_in[0];
    const float* xlst = (const float*)d_in[1];
    const int*   adj  = (const int*)  d_in[2];
    const float* dis  = (const float*)d_in[3];
    const float* Wq = (const float*)d_in[4];
    const float* bq = (const float*)d_in[5];
    const float* Wk = (const float*)d_in[6];
    const float* bk = (const float*)d_in[7];
    const float* Wv = (const float*)d_in[8];
    const float* bv = (const float*)d_in[9];
    const float* W1 = (const float*)d_in[10];
    const float* b1 = (const float*)d_in[11];
    const float* W2 = (const float*)d_in[12];
    const float* b2 = (const float*)d_in[13];
    const float* W3 = (const float*)d_in[14];
    const float* b3 = (const float*)d_in[15];
    const float* g1 = (const float*)d_in[16];
    const float* be1= (const float*)d_in[17];
    const float* g2 = (const float*)d_in[18];
    const float* be2= (const float*)d_in[19];

    float* out_h    = (float*)d_out;                     // [B,N,D]
    float* out_attn = out_h + (size_t)B * N * D;         // [B,N,N]

    void *p_x1 = nullptr, *p_h = nullptr, *p_m1 = nullptr, *p_m2 = nullptr;
    cudaGetSymbolAddress(&p_x1, g_x1);
    cudaGetSymbolAddress(&p_h,  g_h);
    cudaGetSymbolAddress(&p_m1, g_m1);
    cudaGetSymbolAddress(&p_m2, g_m2);
    float* x1 = (float*)p_x1;
    float* h  = (float*)p_h;
    float* m1 = (float*)p_m1;
    float* m2 = (float*)p_m2;

    transpose_kernel<<<dim3(N / 32, D / 32, B), dim3(32, 8)>>>(src);
    conv_qkv_kernel <<<dim3(N / 64, D / 64, B), 256>>>(Wq, Wk, Wv, bq, bk, bv);
    scores_kernel   <<<dim3(N / 64, N / 64, B), 256>>>(dis, adj);
    softmax_kernel  <<<B * N, 256>>>(xlst, out_attn);
    av_kernel       <<<dim3(D / 64, N / 64, B), 256>>>();
    add_ln_kernel   <<<B * N, 256>>>(src, x1, g1, be1, h);
    mlp_kernel      <<<dim3(D / 64, (B * N) / 64), 256>>>(h,  W1, b1, m1, 1);
    mlp_kernel      <<<dim3(D / 64, (B * N) / 64), 256>>>(m1, W2, b2, m2, 1);
    mlp_kernel      <<<dim3(D / 64, (B * N) / 64), 256>>>(m2, W3, b3, x1, 0);
    add_ln_kernel   <<<B * N, 256>>>(h, x1, g2, be2, out_h);
}

// round 2
// speedup vs baseline: 1.0355x; 1.0355x over previous
#include <cuda_runtime.h>
#include <math.h>

#define B 4
#define N 2048
#define D 256
#define KS 16

// ---------------- scratch (device globals: allocation-free) ----------------
__device__ float g_xT[B * D * N];   // src transposed [B][D][N]
__device__ float g_q [B * D * N];
__device__ float g_k [B * D * N];
__device__ float g_v [B * D * N];
__device__ float g_S [(size_t)B * N * N]; // scores -> attn (in place)
__device__ float g_x1[B * N * D];   // attn @ v (row-major [n][d]); reused for m3
__device__ float g_h [B * N * D];
__device__ float g_m1[B * N * D];
__device__ float g_m2[B * N * D];

// ---------------- packed fp32x2 helpers (FFMA2: 2x fp32 per fma-pipe slot) ----------------
typedef unsigned long long u64;
union F2 { u64 u; float f[2]; };

__device__ __forceinline__ u64 ffma2(u64 a, u64 b, u64 c) {
    u64 d;
    asm("fma.rn.f32x2 %0, %1, %2, %3;" : "=l"(d) : "l"(a), "l"(b), "l"(c));
    return d;
}
__device__ __forceinline__ u64 dup2(float x) {
    u64 d;
    unsigned r = __float_as_uint(x);
    asm("mov.b64 %0, {%1, %1};" : "=l"(d) : "r"(r));
    return d;
}

// ---------------- 1. transpose src [B,N,D] -> xT [B,D,N] ----------------
__global__ __launch_bounds__(256) void transpose_kernel(const float* __restrict__ src) {
    __shared__ float tile[32][33];
    int b  = blockIdx.z;
    int n0 = blockIdx.x * 32;
    int c0 = blockIdx.y * 32;
    int tx = threadIdx.x, ty = threadIdx.y; // (32, 8)
#pragma unroll
    for (int i = 0; i < 4; i++)
        tile[ty + i * 8][tx] = src[((size_t)(b * N + n0 + ty + i * 8)) * D + c0 + tx];
    __syncthreads();
#pragma unroll
    for (int i = 0; i < 4; i++)
        g_xT[((size_t)(b * D + c0 + ty + i * 8)) * N + n0 + tx] = tile[tx][ty + i * 8];
}

// ---------------- 2. fused QKV conv1d (K=16, SAME pad: low=7, high=8) ----------------
// q[b,o,n] = bq[o] + sum_c sum_k Wq[o,c,k] * x[b,c,n-7+k]
// FFMA2: accumulators packed over output-channel pairs (w pairs read natively
// from smem as 8B), x broadcast via dup (4 dups amortized over 24 FFMA2 per tap).
__global__ __launch_bounds__(256) void conv_qkv_kernel(
    const float* __restrict__ Wq, const float* __restrict__ Wk, const float* __restrict__ Wv,
    const float* __restrict__ bq, const float* __restrict__ bk, const float* __restrict__ bv)
{
    __shared__ float ws[3][KS][68]; // [mat][k][o], row = 272B (16B aligned)
    __shared__ float xs[80];        // n0-7 .. n0+72
    int b  = blockIdx.z;
    int o0 = blockIdx.y * 64;
    int n0 = blockIdx.x * 64;
    int t  = threadIdx.x;
    int tx = t & 15, ty = t >> 4;   // tx -> n (fast), ty -> o

    u64 acc[3][2][4];               // [mat][o-pair][n], each packed over o parity
#pragma unroll
    for (int m = 0; m < 3; m++)
#pragma unroll
        for (int ii = 0; ii < 2; ii++)
#pragma unroll
            for (int j = 0; j < 4; j++) acc[m][ii][j] = 0ull;

    const float* Wm[3] = {Wq, Wk, Wv};

    for (int c = 0; c < D; c++) {
        if (t < 80) {
            int n = n0 - 7 + t;
            xs[t] = (n >= 0 && n < N) ? g_xT[(size_t)(b * D + c) * N + n] : 0.f;
        }
#pragma unroll
        for (int m = 0; m < 3; m++) {
            const float* W = Wm[m];
#pragma unroll
            for (int r = 0; r < 4; r++) {
                int idx = t + r * 256;          // 0..1023
                int o = idx >> 4, k = idx & 15;
                ws[m][k][o] = W[((size_t)(o0 + o) * D + c) * KS + k];
            }
        }
        __syncthreads();
#pragma unroll
        for (int k = 0; k < KS; k++) {
            u64 xd[4];
#pragma unroll
            for (int j = 0; j < 4; j++) xd[j] = dup2(xs[tx * 4 + j + k]);
#pragma unroll
            for (int m = 0; m < 3; m++) {
                u64 w0 = *(const u64*)&ws[m][k][ty * 4];
                u64 w1 = *(const u64*)&ws[m][k][ty * 4 + 2];
#pragma unroll
                for (int j = 0; j < 4; j++) {
                    acc[m][0][j] = ffma2(w0, xd[j], acc[m][0][j]);
                    acc[m][1][j] = ffma2(w1, xd[j], acc[m][1][j]);
                }
            }
        }
        __syncthreads();
    }

    const float* bm[3] = {bq, bk, bv};
    float* gm[3];
    gm[0] = g_q; gm[1] = g_k; gm[2] = g_v;
#pragma unroll
    for (int ii = 0; ii < 2; ii++)
#pragma unroll
        for (int par = 0; par < 2; par++) {
            int o = o0 + ty * 4 + ii * 2 + par;
#pragma unroll
            for (int m = 0; m < 3; m++) {
                float bv_ = bm[m][o];
                float4 y;
                float* yp = (float*)&y;
#pragma unroll
                for (int j = 0; j < 4; j++) {
                    F2 v; v.u = acc[m][ii][j];
                    yp[j] = v.f[par] + bv_;
                }
                *(float4*)&gm[m][(size_t)(b * D + o) * N + n0 + tx * 4] = y;
            }
        }
}

// ---------------- 3. scores = qT k * scale - dis, masked by adj ----------------
// FFMA2: acc packed over n pairs (q naturally contiguous), dup k.
__global__ __launch_bounds__(256) void scores_kernel(const float* __restrict__ dis,
                                                     const int* __restrict__ adj)
{
    __shared__ float qs[4][64];
    __shared__ float ks[4][64];
    int b  = blockIdx.z;
    int n0 = blockIdx.y * 64;
    int m0 = blockIdx.x * 64;
    int t  = threadIdx.x;
    int tx = t & 15, ty = t >> 4;  // tx -> m (fast), ty -> n
    u64 acc[2][4];                 // [n-pair][m], packed over n parity
#pragma unroll
    for (int ii = 0; ii < 2; ii++)
#pragma unroll
        for (int j = 0; j < 4; j++) acc[ii][j] = 0ull;

    for (int c0 = 0; c0 < D; c0 += 4) {
        int cc = t >> 6, col = t & 63;
        qs[cc][col] = g_q[(size_t)(b * D + c0 + cc) * N + n0 + col];
        ks[cc][col] = g_k[(size_t)(b * D + c0 + cc) * N + m0 + col];
        __syncthreads();
#pragma unroll
        for (int c = 0; c < 4; c++) {
            u64 q0 = *(const u64*)&qs[c][ty * 4];
            u64 q1 = *(const u64*)&qs[c][ty * 4 + 2];
#pragma unroll
            for (int j = 0; j < 4; j++) {
                u64 kd = dup2(ks[c][tx * 4 + j]);
                acc[0][j] = ffma2(q0, kd, acc[0][j]);
                acc[1][j] = ffma2(q1, kd, acc[1][j]);
            }
        }
        __syncthreads();
    }
    const float scale = 0.0625f; // 1/sqrt(256)
#pragma unroll
    for (int ii = 0; ii < 2; ii++)
#pragma unroll
        for (int par = 0; par < 2; par++) {
            int n = n0 + ty * 4 + ii * 2 + par;
            size_t base = ((size_t)b * N + n) * N + m0 + tx * 4;
            float4 d4 = *(const float4*)&dis[base];
            int4   a4 = *(const int4*)&adj[base];
            F2 v0, v1, v2, v3;
            v0.u = acc[ii][0]; v1.u = acc[ii][1]; v2.u = acc[ii][2]; v3.u = acc[ii][3];
            float4 s;
            s.x = (a4.x > 0) ? v0.f[par] * scale - d4.x : -1e9f;
            s.y = (a4.y > 0) ? v1.f[par] * scale - d4.y : -1e9f;
            s.z = (a4.z > 0) ? v2.f[par] * scale - d4.z : -1e9f;
            s.w = (a4.w > 0) ? v3.f[par] * scale - d4.w : -1e9f;
            *(float4*)&g_S[base] = s;
        }
}

// ---------------- 4. row softmax; attn -> g_S (in place); out_attn = x_lst + attn ----------------
__global__ __launch_bounds__(256) void softmax_kernel(const float* __restrict__ xlst,
                                                      float* __restrict__ out_attn)
{
    __shared__ float row[N];
    __shared__ float red[256];
    int r = blockIdx.x;          // b*N + n
    int t = threadIdx.x;
    size_t base = (size_t)r * N;

    float lmax = -1e30f;
    for (int j = t; j < N; j += 256) { float v = g_S[base + j]; row[j] = v; lmax = fmaxf(lmax, v); }
    red[t] = lmax; __syncthreads();
    for (int s = 128; s > 0; s >>= 1) { if (t < s) red[t] = fmaxf(red[t], red[t + s]); __syncthreads(); }
    float mx = red[0];
    __syncthreads();

    float lsum = 0.f;
    for (int j = t; j < N; j += 256) { float e = __expf(row[j] - mx); row[j] = e; lsum += e; }
    red[t] = lsum; __syncthreads();
    for (int s = 128; s > 0; s >>= 1) { if (t < s) red[t] += red[t + s]; __syncthreads(); }
    float inv = 1.f / red[0];

    for (int j = t; j < N; j += 256) {
        float a = row[j] * inv;
        g_S[base + j] = a;
        out_attn[base + j] = xlst[base + j] + a;
    }
}

// ---------------- 5. x1[b,n,c] = sum_m attn[n,m] * v[c,m] ----------------
// FFMA2: packed over k parity — both operands pair natively, zero dup movs.
__global__ __launch_bounds__(256) void av_kernel() {
    __shared__ float As[64][20];
    __shared__ float Vs[64][20];
    int b  = blockIdx.z;
    int n0 = blockIdx.y * 64;
    int c0 = blockIdx.x * 64;
    int t  = threadIdx.x;
    int tx = t & 15, ty = t >> 4;  // tx -> c (fast), ty -> n
    u64 acc[4][4];                 // [n_i][c_j], packed over k parity
#pragma unroll
    for (int i = 0; i < 4; i++)
#pragma unroll
        for (int j = 0; j < 4; j++) acc[i][j] = 0ull;

    int row = t >> 2, seg = t & 3;
    for (int mm = 0; mm < N; mm += 16) {
        *(float4*)&As[row][seg * 4] = *(const float4*)&g_S[((size_t)b * N + n0 + row) * N + mm + seg * 4];
        *(float4*)&Vs[row][seg * 4] = *(const float4*)&g_v[((size_t)b * D + c0 + row) * N + mm + seg * 4];
        __syncthreads();
#pragma unroll
        for (int jg = 0; jg < 4; jg++) {
            u64 aP[4][2], vP[4][2];
#pragma unroll
            for (int i = 0; i < 4; i++) {
                aP[i][0] = *(const u64*)&As[ty * 4 + i][jg * 4];
                aP[i][1] = *(const u64*)&As[ty * 4 + i][jg * 4 + 2];
            }
#pragma unroll
            for (int j = 0; j < 4; j++) {
                vP[j][0] = *(const u64*)&Vs[tx * 4 + j][jg * 4];
                vP[j][1] = *(const u64*)&Vs[tx * 4 + j][jg * 4 + 2];
            }
#pragma unroll
            for (int i = 0; i < 4; i++)
#pragma unroll
                for (int j = 0; j < 4; j++) {
                    acc[i][j] = ffma2(aP[i][0], vP[j][0], acc[i][j]);
                    acc[i][j] = ffma2(aP[i][1], vP[j][1], acc[i][j]);
                }
        }
        __syncthreads();
    }
#pragma unroll
    for (int i = 0; i < 4; i++) {
        size_t base = ((size_t)b * N + n0 + ty * 4 + i) * D + c0 + tx * 4;
        float4 y;
        float* yp = (float*)&y;
#pragma unroll
        for (int j = 0; j < 4; j++) { F2 v; v.u = acc[i][j]; yp[j] = v.f[0] + v.f[1]; }
        *(float4*)&g_x1[base] = y;
    }
}

// ---------------- 6. out = LayerNorm(A + Bsrc) * g + be ----------------
__global__ __launch_bounds__(256) void add_ln_kernel(const float* __restrict__ A,
                                                     const float* __restrict__ Bsrc,
                                                     const float* __restrict__ g,
                                                     const float* __restrict__ be,
                                                     float* __restrict__ outp)
{
    __shared__ float red[256];
    int r = blockIdx.x, t = threadIdx.x;
    size_t base = (size_t)r * D;
    float x = A[base + t] + Bsrc[base + t];
    red[t] = x; __syncthreads();
    for (int s = 128; s > 0; s >>= 1) { if (t < s) red[t] += red[t + s]; __syncthreads(); }
    float mu = red[0] * (1.f / D);
    __syncthreads();
    float dv = x - mu;
    red[t] = dv * dv; __syncthreads();
    for (int s = 128; s > 0; s >>= 1) { if (t < s) red[t] += red[t + s]; __syncthreads(); }
    float var = red[0] * (1.f / D);
    outp[base + t] = dv * rsqrtf(var + 1e-5f) * g[t] + be[t];
}

// ---------------- 7. Y[n,o] = act(sum_c X[n,c] * W[o,c] + b[o]) ----------------
__global__ __launch_bounds__(256) void mlp_kernel(const float* __restrict__ X,
                                                  const float* __restrict__ W,
                                                  const float* __restrict__ bias,
                                                  float* __restrict__ Y, int leaky)
{
    __shared__ float Xs[64][20];
    __shared__ float Ws[64][20];
    int r0 = blockIdx.y * 64;  // over B*N rows
    int o0 = blockIdx.x * 64;
    int t  = threadIdx.x;
    int tx = t & 15, ty = t >> 4;  // tx -> o (fast), ty -> n
    u64 acc[4][4];
#pragma unroll
    for (int i = 0; i < 4; i++)
#pragma unroll
        for (int j = 0; j < 4; j++) acc[i][j] = 0ull;

    int row = t >> 2, seg = t & 3;
    for (int cc = 0; cc < D; cc += 16) {
        *(float4*)&Xs[row][seg * 4] = *(const float4*)&X[(size_t)(r0 + row) * D + cc + seg * 4];
        *(float4*)&Ws[row][seg * 4] = *(const float4*)&W[(size_t)(o0 + row) * D + cc + seg * 4];
        __syncthreads();
#pragma unroll
        for (int jg = 0; jg < 4; jg++) {
            u64 xP[4][2], wP[4][2];
#pragma unroll
            for (int i = 0; i < 4; i++) {
                xP[i][0] = *(const u64*)&Xs[ty * 4 + i][jg * 4];
                xP[i][1] = *(const u64*)&Xs[ty * 4 + i][jg * 4 + 2];
            }
#pragma unroll
            for (int j = 0; j < 4; j++) {
                wP[j][0] = *(const u64*)&Ws[tx * 4 + j][jg * 4];
                wP[j][1] = *(const u64*)&Ws[tx * 4 + j][jg * 4 + 2];
            }
#pragma unroll
            for (int i = 0; i < 4; i++)
#pragma unroll
                for (int j = 0; j < 4; j++) {
                    acc[i][j] = ffma2(xP[i][0], wP[j][0], acc[i][j]);
                    acc[i][j] = ffma2(xP[i][1], wP[j][1], acc[i][j]);
                }
        }
        __syncthreads();
    }
    float4 b4 = *(const float4*)&bias[o0 + tx * 4];
    float ba[4] = {b4.x, b4.y, b4.z, b4.w};
#pragma unroll
    for (int i = 0; i < 4; i++) {
        float4 y;
        float* yp = (float*)&y;
#pragma unroll
        for (int j = 0; j < 4; j++) {
            F2 v; v.u = acc[i][j];
            float s = v.f[0] + v.f[1] + ba[j];
            if (leaky) s = (s > 0.f) ? s : 0.01f * s;
            yp[j] = s;
        }
        *(float4*)&Y[(size_t)(r0 + ty * 4 + i) * D + o0 + tx * 4] = y;
    }
}

// ---------------- launch ----------------
extern "C" void kernel_launch(void* const* d_in, const int* in_sizes, int n_in,
                              void* d_out, int out_size) {
    const float* src  = (const float*)d_in[0];
    const float* xlst = (const float*)d_in[1];
    const int*   adj  = (const int*)  d_in[2];
    const float* dis  = (const float*)d_in[3];
    const float* Wq = (const float*)d_in[4];
    const float* bq = (const float*)d_in[5];
    const float* Wk = (const float*)d_in[6];
    const float* bk = (const float*)d_in[7];
    const float* Wv = (const float*)d_in[8];
    const float* bv = (const float*)d_in[9];
    const float* W1 = (const float*)d_in[10];
    const float* b1 = (const float*)d_in[11];
    const float* W2 = (const float*)d_in[12];
    const float* b2 = (const float*)d_in[13];
    const float* W3 = (const float*)d_in[14];
    const float* b3 = (const float*)d_in[15];
    const float* g1 = (const float*)d_in[16];
    const float* be1= (const float*)d_in[17];
    const float* g2 = (const float*)d_in[18];
    const float* be2= (const float*)d_in[19];

    float* out_h    = (float*)d_out;                     // [B,N,D]
    float* out_attn = out_h + (size_t)B * N * D;         // [B,N,N]

    void *p_x1 = nullptr, *p_h = nullptr, *p_m1 = nullptr, *p_m2 = nullptr;
    cudaGetSymbolAddress(&p_x1, g_x1);
    cudaGetSymbolAddress(&p_h,  g_h);
    cudaGetSymbolAddress(&p_m1, g_m1);
    cudaGetSymbolAddress(&p_m2, g_m2);
    float* x1 = (float*)p_x1;
    float* h  = (float*)p_h;
    float* m1 = (float*)p_m1;
    float* m2 = (float*)p_m2;

    transpose_kernel<<<dim3(N / 32, D / 32, B), dim3(32, 8)>>>(src);
    conv_qkv_kernel <<<dim3(N / 64, D / 64, B), 256>>>(Wq, Wk, Wv, bq, bk, bv);
    scores_kernel   <<<dim3(N / 64, N / 64, B), 256>>>(dis, adj);
    softmax_kernel  <<<B * N, 256>>>(xlst, out_attn);
    av_kernel       <<<dim3(D / 64, N / 64, B), 256>>>();
    add_ln_kernel   <<<B * N, 256>>>(src, x1, g1, be1, h);
    mlp_kernel      <<<dim3(D / 64, (B * N) / 64), 256>>>(h,  W1, b1, m1, 1);
    mlp_kernel      <<<dim3(D / 64, (B * N) / 64), 256>>>(m1, W2, b2, m2, 1);
    mlp_kernel      <<<dim3(D / 64, (B * N) / 64), 256>>>(m2, W3, b3, x1, 0);
    add_ln_kernel   <<<B * N, 256>>>(h, x1, g2, be2, out_h);
}

// round 4
// speedup vs baseline: 1.4256x; 1.3767x over previous
#include <cuda_runtime.h>
#include <cuda_bf16.h>
#include <math.h>
#include <stdint.h>

#define B 4
#define N 2048
#define D 256
#define KS 16

// ---------------- scratch (device globals: allocation-free) ----------------
__device__ float g_q [B * D * N];
__device__ float g_k [B * D * N];
__device__ float g_v [B * D * N];
__device__ float g_S [(size_t)B * N * N]; // scores -> attn (in place)
__device__ float g_x1[B * N * D];
__device__ float g_h [B * N * D];
__device__ float g_m1[B * N * D];
__device__ float g_m2[B * N * D];
// bf16 split operands for tensor-core conv
__device__ __align__(16) __nv_bfloat16 g_xh[B * N * D];
__device__ __align__(16) __nv_bfloat16 g_xl[B * N * D];
__device__ __align__(16) __nv_bfloat16 g_wh[3 * KS * D * D]; // [mat][k][o][c]
__device__ __align__(16) __nv_bfloat16 g_wl[3 * KS * D * D];

// ---------------- packed fp32x2 helpers ----------------
typedef unsigned long long u64;
union F2 { u64 u; float f[2]; };
__device__ __forceinline__ u64 ffma2(u64 a, u64 b, u64 c) {
    u64 d;
    asm("fma.rn.f32x2 %0, %1, %2, %3;" : "=l"(d) : "l"(a), "l"(b), "l"(c));
    return d;
}
__device__ __forceinline__ u64 dup2(float x) {
    u64 d;
    unsigned r = __float_as_uint(x);
    asm("mov.b64 %0, {%1, %1};" : "=l"(d) : "r"(r));
    return d;
}

// ---------------- generic-PTX tensor core helpers (HMMA path) ----------------
__device__ __forceinline__ uint32_t smem_u32(const void* p) {
    uint32_t a;
    asm("{ .reg .u64 t; cvta.to.shared.u64 t, %1; cvt.u32.u64 %0, t; }" : "=r"(a) : "l"(p));
    return a;
}
__device__ __forceinline__ void ldsm_x4(uint32_t* r, uint32_t addr) {
    asm volatile("ldmatrix.sync.aligned.m8n8.x4.shared.b16 {%0,%1,%2,%3}, [%4];"
                 : "=r"(r[0]), "=r"(r[1]), "=r"(r[2]), "=r"(r[3]) : "r"(addr));
}
__device__ __forceinline__ void ldsm_x2(uint32_t* r, uint32_t addr) {
    asm volatile("ldmatrix.sync.aligned.m8n8.x2.shared.b16 {%0,%1}, [%2];"
                 : "=r"(r[0]), "=r"(r[1]) : "r"(addr));
}
__device__ __forceinline__ void mma16816(float* d, const uint32_t* a, const uint32_t* b) {
    asm volatile(
        "mma.sync.aligned.m16n8k16.row.col.f32.bf16.bf16.f32 "
        "{%0,%1,%2,%3}, {%4,%5,%6,%7}, {%8,%9}, {%0,%1,%2,%3};"
        : "+f"(d[0]), "+f"(d[1]), "+f"(d[2]), "+f"(d[3])
        : "r"(a[0]), "r"(a[1]), "r"(a[2]), "r"(a[3]), "r"(b[0]), "r"(b[1]));
}

// ---------------- prep: split src into bf16 hi/lo ----------------
__global__ __launch_bounds__(256) void prep_x_kernel(const float* __restrict__ src) {
    int i = blockIdx.x * 256 + threadIdx.x;
    float f = src[i];
    __nv_bfloat16 h = __float2bfloat16_rn(f);
    g_xh[i] = h;
    g_xl[i] = __float2bfloat16_rn(f - __bfloat162float(h));
}

// ---------------- prep: W [o][c][k] -> [k][o][c], split hi/lo ----------------
__global__ __launch_bounds__(256) void prep_w_kernel(const float* __restrict__ Wq,
                                                     const float* __restrict__ Wk,
                                                     const float* __restrict__ Wv) {
    int i = blockIdx.x * 256 + threadIdx.x;   // [k][o][c]
    int mat = blockIdx.y;
    const float* W = (mat == 0) ? Wq : (mat == 1) ? Wk : Wv;
    int c = i & 255, o = (i >> 8) & 255, k = i >> 16;
    float f = W[((size_t)(o * D + c)) * KS + k];
    __nv_bfloat16 h = __float2bfloat16_rn(f);
    size_t oidx = (size_t)mat * KS * D * D + i;
    g_wh[oidx] = h;
    g_wl[oidx] = __float2bfloat16_rn(f - __bfloat162float(h));
}

// ---------------- HMMA conv: out[o0..o0+127][n0..n0+127] for (mat, b) ----------------
// smem rows padded to 144B (72 bf16) -> conflict-free ldmatrix/stores.
#define ROWB 144
#define S_AH 0
#define S_AL 18432
#define S_BH 36864
#define S_BL 57600
#define CONV_SMEM 78336

__global__ __launch_bounds__(256) void conv_mma_kernel(const float* __restrict__ bq,
                                                       const float* __restrict__ bk,
                                                       const float* __restrict__ bv) {
    extern __shared__ char sm[];
    const uint32_t sbase = smem_u32(sm);
    const int t = threadIdx.x;
    const int lane = t & 31, wid = t >> 5;
    const int n0 = blockIdx.x * 128;
    const int o0 = blockIdx.y * 128;
    const int mat = blockIdx.z >> 2;
    const int b   = blockIdx.z & 3;
    const int warp_o = (wid & 1) * 64;
    const int warp_n = (wid >> 1) * 32;

    const __nv_bfloat16* Ah = g_wh + (size_t)mat * KS * D * D;
    const __nv_bfloat16* Al = g_wl + (size_t)mat * KS * D * D;
    const __nv_bfloat16* Xh = g_xh + (size_t)b * N * D;
    const __nv_bfloat16* Xl = g_xl + (size_t)b * N * D;

    float acc[4][4][4]; // [ot][nt][reg]
#pragma unroll
    for (int i = 0; i < 4; i++)
#pragma unroll
        for (int j = 0; j < 4; j++)
#pragma unroll
            for (int r = 0; r < 4; r++) acc[i][j][r] = 0.f;

    for (int cc = 0; cc < 4; cc++) {
        int c64 = cc * 64;
        for (int k = 0; k < KS; k++) {
            __syncthreads(); // previous compute finished; smem reusable
            if (k == 0) {
                // B tiles: 144 rows (n0-7 .. n0+136) x 64 c, hi+lo
                for (int ch = t; ch < 1152; ch += 256) {
                    int row = ch >> 3, q = ch & 7;
                    int n = n0 - 7 + row;
                    uint32_t off = (uint32_t)(row * ROWB + q * 16);
                    if (n >= 0 && n < N) {
                        size_t gi = (size_t)n * D + c64 + q * 8;
                        *(uint4*)(sm + S_BH + off) = *(const uint4*)(Xh + gi);
                        *(uint4*)(sm + S_BL + off) = *(const uint4*)(Xl + gi);
                    } else {
                        uint4 z = {0u, 0u, 0u, 0u};
                        *(uint4*)(sm + S_BH + off) = z;
                        *(uint4*)(sm + S_BL + off) = z;
                    }
                }
            }
            // A tiles: 128 rows (o) x 64 c for tap k, hi+lo
            for (int ch = t; ch < 1024; ch += 256) {
                int row = ch >> 3, q = ch & 7;
                uint32_t off = (uint32_t)(row * ROWB + q * 16);
                size_t gi = ((size_t)(k * D + o0 + row)) * D + c64 + q * 8;
                *(uint4*)(sm + S_AH + off) = *(const uint4*)(Ah + gi);
                *(uint4*)(sm + S_AL + off) = *(const uint4*)(Al + gi);
            }
            __syncthreads();

#pragma unroll
            for (int kc = 0; kc < 4; kc++) {
                // A frags (4 o-subtiles of 16): ldmatrix x4 (hi, lo)
                uint32_t ah[4][4], al[4][4];
                {
                    int arow = warp_o + (lane & 15);
                    int acol = kc * 16 + ((lane >> 4) << 3);
                    uint32_t abase = sbase + (uint32_t)(arow * ROWB + acol * 2);
#pragma unroll
                    for (int ot = 0; ot < 4; ot++) {
                        ldsm_x4(ah[ot], abase + S_AH + ot * 16 * ROWB);
                        ldsm_x4(al[ot], abase + S_AL + ot * 16 * ROWB);
                    }
                }
                // B frags (4 n-subtiles of 8): ldmatrix x2 (hi, lo), rows shifted by k
                uint32_t bh[4][2], bl[4][2];
                {
                    int brow = warp_n + (lane & 7) + k;
                    int bcol = kc * 16 + (lane & 8);
                    uint32_t bbase = sbase + (uint32_t)(brow * ROWB + bcol * 2);
#pragma unroll
                    for (int nt = 0; nt < 4; nt++) {
                        ldsm_x2(bh[nt], bbase + S_BH + nt * 8 * ROWB);
                        ldsm_x2(bl[nt], bbase + S_BL + nt * 8 * ROWB);
                    }
                }
#pragma unroll
                for (int ot = 0; ot < 4; ot++)
#pragma unroll
                    for (int nt = 0; nt < 4; nt++) {
                        mma16816(acc[ot][nt], ah[ot], bh[nt]);
                        mma16816(acc[ot][nt], ah[ot], bl[nt]);
                        mma16816(acc[ot][nt], al[ot], bh[nt]);
                    }
            }
        }
    }

    const float* bias = (mat == 0) ? bq : (mat == 1) ? bk : bv;
    float* out = (mat == 0) ? g_q : (mat == 1) ? g_k : g_v;
    int g = lane >> 2, cpair = (lane & 3) * 2;
#pragma unroll
    for (int ot = 0; ot < 4; ot++) {
        int o_lo = o0 + warp_o + ot * 16 + g;
        float bv0 = bias[o_lo];
        float bv1 = bias[o_lo + 8];
#pragma unroll
        for (int nt = 0; nt < 4; nt++) {
            int ncol = n0 + warp_n + nt * 8 + cpair;
            float2 y0 = {acc[ot][nt][0] + bv0, acc[ot][nt][1] + bv0};
            float2 y1 = {acc[ot][nt][2] + bv1, acc[ot][nt][3] + bv1};
            *(float2*)&out[(size_t)(b * D + o_lo) * N + ncol] = y0;
            *(float2*)&out[(size_t)(b * D + o_lo + 8) * N + ncol] = y1;
        }
    }
}

// ---------------- 3. scores = qT k * scale - dis, masked by adj (FFMA2) ----------------
__global__ __launch_bounds__(256) void scores_kernel(const float* __restrict__ dis,
                                                     const int* __restrict__ adj)
{
    __shared__ float qs[4][64];
    __shared__ float ks[4][64];
    int b  = blockIdx.z;
    int n0 = blockIdx.y * 64;
    int m0 = blockIdx.x * 64;
    int t  = threadIdx.x;
    int tx = t & 15, ty = t >> 4;
    u64 acc[2][4];
#pragma unroll
    for (int ii = 0; ii < 2; ii++)
#pragma unroll
        for (int j = 0; j < 4; j++) acc[ii][j] = 0ull;

    for (int c0 = 0; c0 < D; c0 += 4) {
        int cc = t >> 6, col = t & 63;
        qs[cc][col] = g_q[(size_t)(b * D + c0 + cc) * N + n0 + col];
        ks[cc][col] = g_k[(size_t)(b * D + c0 + cc) * N + m0 + col];
        __syncthreads();
#pragma unroll
        for (int c = 0; c < 4; c++) {
            u64 q0 = *(const u64*)&qs[c][ty * 4];
            u64 q1 = *(const u64*)&qs[c][ty * 4 + 2];
#pragma unroll
            for (int j = 0; j < 4; j++) {
                u64 kd = dup2(ks[c][tx * 4 + j]);
                acc[0][j] = ffma2(q0, kd, acc[0][j]);
                acc[1][j] = ffma2(q1, kd, acc[1][j]);
            }
        }
        __syncthreads();
    }
    const float scale = 0.0625f;
#pragma unroll
    for (int ii = 0; ii < 2; ii++)
#pragma unroll
        for (int par = 0; par < 2; par++) {
            int n = n0 + ty * 4 + ii * 2 + par;
            size_t base = ((size_t)b * N + n) * N + m0 + tx * 4;
            float4 d4 = *(const float4*)&dis[base];
            int4   a4 = *(const int4*)&adj[base];
            F2 v0, v1, v2, v3;
            v0.u = acc[ii][0]; v1.u = acc[ii][1]; v2.u = acc[ii][2]; v3.u = acc[ii][3];
            float4 s;
            s.x = (a4.x > 0) ? v0.f[par] * scale - d4.x : -1e9f;
            s.y = (a4.y > 0) ? v1.f[par] * scale - d4.y : -1e9f;
            s.z = (a4.z > 0) ? v2.f[par] * scale - d4.z : -1e9f;
            s.w = (a4.w > 0) ? v3.f[par] * scale - d4.w : -1e9f;
            *(float4*)&g_S[base] = s;
        }
}

// ---------------- 4. row softmax ----------------
__global__ __launch_bounds__(256) void softmax_kernel(const float* __restrict__ xlst,
                                                      float* __restrict__ out_attn)
{
    __shared__ float row[N];
    __shared__ float red[256];
    int r = blockIdx.x;
    int t = threadIdx.x;
    size_t base = (size_t)r * N;

    float lmax = -1e30f;
    for (int j = t; j < N; j += 256) { float v = g_S[base + j]; row[j] = v; lmax = fmaxf(lmax, v); }
    red[t] = lmax; __syncthreads();
    for (int s = 128; s > 0; s >>= 1) { if (t < s) red[t] = fmaxf(red[t], red[t + s]); __syncthreads(); }
    float mx = red[0];
    __syncthreads();

    float lsum = 0.f;
    for (int j = t; j < N; j += 256) { float e = __expf(row[j] - mx); row[j] = e; lsum += e; }
    red[t] = lsum; __syncthreads();
    for (int s = 128; s > 0; s >>= 1) { if (t < s) red[t] += red[t + s]; __syncthreads(); }
    float inv = 1.f / red[0];

    for (int j = t; j < N; j += 256) {
        float a = row[j] * inv;
        g_S[base + j] = a;
        out_attn[base + j] = xlst[base + j] + a;
    }
}

// ---------------- 5. x1[b,n,c] = sum_m attn[n,m] * v[c,m] (FFMA2) ----------------
__global__ __launch_bounds__(256) void av_kernel() {
    __shared__ float As[64][20];
    __shared__ float Vs[64][20];
    int b  = blockIdx.z;
    int n0 = blockIdx.y * 64;
    int c0 = blockIdx.x * 64;
    int t  = threadIdx.x;
    int tx = t & 15, ty = t >> 4;
    u64 acc[4][4];
#pragma unroll
    for (int i = 0; i < 4; i++)
#pragma unroll
        for (int j = 0; j < 4; j++) acc[i][j] = 0ull;

    int row = t >> 2, seg = t & 3;
    for (int mm = 0; mm < N; mm += 16) {
        *(float4*)&As[row][seg * 4] = *(const float4*)&g_S[((size_t)b * N + n0 + row) * N + mm + seg * 4];
        *(float4*)&Vs[row][seg * 4] = *(const float4*)&g_v[((size_t)b * D + c0 + row) * N + mm + seg * 4];
        __syncthreads();
#pragma unroll
        for (int jg = 0; jg < 4; jg++) {
            u64 aP[4][2], vP[4][2];
#pragma unroll
            for (int i = 0; i < 4; i++) {
                aP[i][0] = *(const u64*)&As[ty * 4 + i][jg * 4];
                aP[i][1] = *(const u64*)&As[ty * 4 + i][jg * 4 + 2];
            }
#pragma unroll
            for (int j = 0; j < 4; j++) {
                vP[j][0] = *(const u64*)&Vs[tx * 4 + j][jg * 4];
                vP[j][1] = *(const u64*)&Vs[tx * 4 + j][jg * 4 + 2];
            }
#pragma unroll
            for (int i = 0; i < 4; i++)
#pragma unroll
                for (int j = 0; j < 4; j++) {
                    acc[i][j] = ffma2(aP[i][0], vP[j][0], acc[i][j]);
                    acc[i][j] = ffma2(aP[i][1], vP[j][1], acc[i][j]);
                }
        }
        __syncthreads();
    }
#pragma unroll
    for (int i = 0; i < 4; i++) {
        size_t base = ((size_t)b * N + n0 + ty * 4 + i) * D + c0 + tx * 4;
        float4 y;
        float* yp = (float*)&y;
#pragma unroll
        for (int j = 0; j < 4; j++) { F2 v; v.u = acc[i][j]; yp[j] = v.f[0] + v.f[1]; }
        *(float4*)&g_x1[base] = y;
    }
}

// ---------------- 6. out = LayerNorm(A + Bsrc) * g + be ----------------
__global__ __launch_bounds__(256) void add_ln_kernel(const float* __restrict__ A,
                                                     const float* __restrict__ Bsrc,
                                                     const float* __restrict__ g,
                                                     const float* __restrict__ be,
                                                     float* __restrict__ outp)
{
    __shared__ float red[256];
    int r = blockIdx.x, t = threadIdx.x;
    size_t base = (size_t)r * D;
    float x = A[base + t] + Bsrc[base + t];
    red[t] = x; __syncthreads();
    for (int s = 128; s > 0; s >>= 1) { if (t < s) red[t] += red[t + s]; __syncthreads(); }
    float mu = red[0] * (1.f / D);
    __syncthreads();
    float dv = x - mu;
    red[t] = dv * dv; __syncthreads();
    for (int s = 128; s > 0; s >>= 1) { if (t < s) red[t] += red[t + s]; __syncthreads(); }
    float var = red[0] * (1.f / D);
    outp[base + t] = dv * rsqrtf(var + 1e-5f) * g[t] + be[t];
}

// ---------------- 7. MLP GEMM (FFMA2) ----------------
__global__ __launch_bounds__(256) void mlp_kernel(const float* __restrict__ X,
                                                  const float* __restrict__ W,
                                                  const float* __restrict__ bias,
                                                  float* __restrict__ Y, int leaky)
{
    __shared__ float Xs[64][20];
    __shared__ float Ws[64][20];
    int r0 = blockIdx.y * 64;
    int o0 = blockIdx.x * 64;
    int t  = threadIdx.x;
    int tx = t & 15, ty = t >> 4;
    u64 acc[4][4];
#pragma unroll
    for (int i = 0; i < 4; i++)
#pragma unroll
        for (int j = 0; j < 4; j++) acc[i][j] = 0ull;

    int row = t >> 2, seg = t & 3;
    for (int cc = 0; cc < D; cc += 16) {
        *(float4*)&Xs[row][seg * 4] = *(const float4*)&X[(size_t)(r0 + row) * D + cc + seg * 4];
        *(float4*)&Ws[row][seg * 4] = *(const float4*)&W[(size_t)(o0 + row) * D + cc + seg * 4];
        __syncthreads();
#pragma unroll
        for (int jg = 0; jg < 4; jg++) {
            u64 xP[4][2], wP[4][2];
#pragma unroll
            for (int i = 0; i < 4; i++) {
                xP[i][0] = *(const u64*)&Xs[ty * 4 + i][jg * 4];
                xP[i][1] = *(const u64*)&Xs[ty * 4 + i][jg * 4 + 2];
            }
#pragma unroll
            for (int j = 0; j < 4; j++) {
                wP[j][0] = *(const u64*)&Ws[tx * 4 + j][jg * 4];
                wP[j][1] = *(const u64*)&Ws[tx * 4 + j][jg * 4 + 2];
            }
#pragma unroll
            for (int i = 0; i < 4; i++)
#pragma unroll
                for (int j = 0; j < 4; j++) {
                    acc[i][j] = ffma2(xP[i][0], wP[j][0], acc[i][j]);
                    acc[i][j] = ffma2(xP[i][1], wP[j][1], acc[i][j]);
                }
        }
        __syncthreads();
    }
    float4 b4 = *(const float4*)&bias[o0 + tx * 4];
    float ba[4] = {b4.x, b4.y, b4.z, b4.w};
#pragma unroll
    for (int i = 0; i < 4; i++) {
        float4 y;
        float* yp = (float*)&y;
#pragma unroll
        for (int j = 0; j < 4; j++) {
            F2 v; v.u = acc[i][j];
            float s = v.f[0] + v.f[1] + ba[j];
            if (leaky) s = (s > 0.f) ? s : 0.01f * s;
            yp[j] = s;
        }
        *(float4*)&Y[(size_t)(r0 + ty * 4 + i) * D + o0 + tx * 4] = y;
    }
}

// ---------------- launch ----------------
extern "C" void kernel_launch(void* const* d_in, const int* in_sizes, int n_in,
                              void* d_out, int out_size) {
    const float* src  = (const float*)d_in[0];
    const float* xlst = (const float*)d_in[1];
    const int*   adj  = (const int*)  d_in[2];
    const float* dis  = (const float*)d_in[3];
    const float* Wq = (const float*)d_in[4];
    const float* bq = (const float*)d_in[5];
    const float* Wk = (const float*)d_in[6];
    const float* bk = (const float*)d_in[7];
    const float* Wv = (const float*)d_in[8];
    const float* bv = (const float*)d_in[9];
    const float* W1 = (const float*)d_in[10];
    const float* b1 = (const float*)d_in[11];
    const float* W2 = (const float*)d_in[12];
    const float* b2 = (const float*)d_in[13];
    const float* W3 = (const float*)d_in[14];
    const float* b3 = (const float*)d_in[15];
    const float* g1 = (const float*)d_in[16];
    const float* be1= (const float*)d_in[17];
    const float* g2 = (const float*)d_in[18];
    const float* be2= (const float*)d_in[19];

    float* out_h    = (float*)d_out;
    float* out_attn = out_h + (size_t)B * N * D;

    void *p_x1 = nullptr, *p_h = nullptr, *p_m1 = nullptr, *p_m2 = nullptr;
    cudaGetSymbolAddress(&p_x1, g_x1);
    cudaGetSymbolAddress(&p_h,  g_h);
    cudaGetSymbolAddress(&p_m1, g_m1);
    cudaGetSymbolAddress(&p_m2, g_m2);
    float* x1 = (float*)p_x1;
    float* h  = (float*)p_h;
    float* m1 = (float*)p_m1;
    float* m2 = (float*)p_m2;

    cudaFuncSetAttribute(conv_mma_kernel, cudaFuncAttributeMaxDynamicSharedMemorySize, CONV_SMEM);

    prep_x_kernel  <<<(B * N * D) / 256, 256>>>(src);
    prep_w_kernel  <<<dim3((KS * D * D) / 256, 3), 256>>>(Wq, Wk, Wv);
    conv_mma_kernel<<<dim3(N / 128, 2, 12), 256, CONV_SMEM>>>(bq, bk, bv);
    scores_kernel  <<<dim3(N / 64, N / 64, B), 256>>>(dis, adj);
    softmax_kernel <<<B * N, 256>>>(xlst, out_attn);
    av_kernel      <<<dim3(D / 64, N / 64, B), 256>>>();
    add_ln_kernel  <<<B * N, 256>>>(src, x1, g1, be1, h);
    mlp_kernel     <<<dim3(D / 64, (B * N) / 64), 256>>>(h,  W1, b1, m1, 1);
    mlp_kernel     <<<dim3(D / 64, (B * N) / 64), 256>>>(m1, W2, b2, m2, 1);
    mlp_kernel     <<<dim3(D / 64, (B * N) / 64), 256>>>(m2, W3, b3, x1, 0);
    add_ln_kernel  <<<B * N, 256>>>(h, x1, g2, be2, out_h);
}

// round 5
// speedup vs baseline: 2.9760x; 2.0875x over previous
#include <cuda_runtime.h>
#include <cuda_bf16.h>
#include <math.h>
#include <stdint.h>

#define B 4
#define N 2048
#define D 256
#define KS 16

typedef unsigned long long u64;

// ---------------- scratch (device globals: allocation-free) ----------------
__device__ float g_S [(size_t)B * N * N]; // masked scores (softmax input)
__device__ float g_x1[B * N * D];         // attn@v result; reused for m3
__device__ float g_h [B * N * D];
// conv inputs (bf16 split)
__device__ __align__(16) __nv_bfloat16 g_xh[B * N * D];
__device__ __align__(16) __nv_bfloat16 g_xl[B * N * D];
__device__ __align__(16) __nv_bfloat16 g_wh[3 * KS * D * D]; // [mat][k][o][c]
__device__ __align__(16) __nv_bfloat16 g_wl[3 * KS * D * D];
// conv outputs (bf16 split)
__device__ __align__(16) __nv_bfloat16 g_qh[B * N * D];  // [b][n][c]
__device__ __align__(16) __nv_bfloat16 g_ql[B * N * D];
__device__ __align__(16) __nv_bfloat16 g_kh[B * N * D];  // [b][n][c]
__device__ __align__(16) __nv_bfloat16 g_kl[B * N * D];
__device__ __align__(16) __nv_bfloat16 g_vh[B * D * N];  // [b][c][n]
__device__ __align__(16) __nv_bfloat16 g_vl[B * D * N];
// attn (bf16 split)
__device__ __align__(16) __nv_bfloat16 g_ah[(size_t)B * N * N];
__device__ __align__(16) __nv_bfloat16 g_al[(size_t)B * N * N];
// MLP activations (bf16 split) + weights
__device__ __align__(16) __nv_bfloat16 g_hh[B * N * D];
__device__ __align__(16) __nv_bfloat16 g_hl[B * N * D];
__device__ __align__(16) __nv_bfloat16 g_m1h[B * N * D];
__device__ __align__(16) __nv_bfloat16 g_m1l[B * N * D];
__device__ __align__(16) __nv_bfloat16 g_m2h[B * N * D];
__device__ __align__(16) __nv_bfloat16 g_m2l[B * N * D];
__device__ __align__(16) __nv_bfloat16 g_w123h[3 * D * D];
__device__ __align__(16) __nv_bfloat16 g_w123l[3 * D * D];

// ---------------- generic-PTX tensor core helpers ----------------
__device__ __forceinline__ uint32_t smem_u32(const void* p) {
    uint32_t a;
    asm("{ .reg .u64 t; cvta.to.shared.u64 t, %1; cvt.u32.u64 %0, t; }" : "=r"(a) : "l"(p));
    return a;
}
__device__ __forceinline__ void ldsm_x4(uint32_t* r, uint32_t addr) {
    asm volatile("ldmatrix.sync.aligned.m8n8.x4.shared.b16 {%0,%1,%2,%3}, [%4];"
                 : "=r"(r[0]), "=r"(r[1]), "=r"(r[2]), "=r"(r[3]) : "r"(addr));
}
__device__ __forceinline__ void ldsm_x2(uint32_t* r, uint32_t addr) {
    asm volatile("ldmatrix.sync.aligned.m8n8.x2.shared.b16 {%0,%1}, [%2];"
                 : "=r"(r[0]), "=r"(r[1]) : "r"(addr));
}
__device__ __forceinline__ void mma16816(float* d, const uint32_t* a, const uint32_t* b) {
    asm volatile(
        "mma.sync.aligned.m16n8k16.row.col.f32.bf16.bf16.f32 "
        "{%0,%1,%2,%3}, {%4,%5,%6,%7}, {%8,%9}, {%0,%1,%2,%3};"
        : "+f"(d[0]), "+f"(d[1]), "+f"(d[2]), "+f"(d[3])
        : "r"(a[0]), "r"(a[1]), "r"(a[2]), "r"(a[3]), "r"(b[0]), "r"(b[1]));
}
__device__ __forceinline__ void split_bf16(float f, __nv_bfloat16& h, __nv_bfloat16& l) {
    h = __float2bfloat16_rn(f);
    l = __float2bfloat16_rn(f - __bfloat162float(h));
}

// ---------------- prep kernels ----------------
__global__ __launch_bounds__(256) void prep_x_kernel(const float* __restrict__ src) {
    int i = blockIdx.x * 256 + threadIdx.x;
    split_bf16(src[i], g_xh[i], g_xl[i]);
}
__global__ __launch_bounds__(256) void prep_w_kernel(const float* __restrict__ Wq,
                                                     const float* __restrict__ Wk,
                                                     const float* __restrict__ Wv) {
    int i = blockIdx.x * 256 + threadIdx.x;   // [k][o][c]
    int mat = blockIdx.y;
    const float* W = (mat == 0) ? Wq : (mat == 1) ? Wk : Wv;
    int c = i & 255, o = (i >> 8) & 255, k = i >> 16;
    float f = W[((size_t)(o * D + c)) * KS + k];
    size_t oi = (size_t)mat * KS * D * D + i;
    split_bf16(f, g_wh[oi], g_wl[oi]);
}
__global__ __launch_bounds__(256) void prep_w2_kernel(const float* __restrict__ W1,
                                                      const float* __restrict__ W2,
                                                      const float* __restrict__ W3) {
    int i = blockIdx.x * 256 + threadIdx.x;   // [o][c]
    int mat = blockIdx.y;
    const float* W = (mat == 0) ? W1 : (mat == 1) ? W2 : W3;
    size_t oi = (size_t)mat * D * D + i;
    split_bf16(W[i], g_w123h[oi], g_w123l[oi]);
}

// ---------------- HMMA conv: per (mat,b): out[o0..127][n0..127] ----------------
#define ROWB 144
#define S_AH 0
#define S_AL 18432
#define S_BH 36864
#define S_BL 57600
#define CONV_SMEM 78336

__global__ __launch_bounds__(256) void conv_mma_kernel(const float* __restrict__ bq,
                                                       const float* __restrict__ bk,
                                                       const float* __restrict__ bv) {
    extern __shared__ char sm[];
    const uint32_t sbase = smem_u32(sm);
    const int t = threadIdx.x;
    const int lane = t & 31, wid = t >> 5;
    const int n0 = blockIdx.x * 128;
    const int o0 = blockIdx.y * 128;
    const int mat = blockIdx.z >> 2;
    const int b   = blockIdx.z & 3;
    const int warp_o = (wid & 1) * 64;
    const int warp_n = (wid >> 1) * 32;

    const __nv_bfloat16* Ah = g_wh + (size_t)mat * KS * D * D;
    const __nv_bfloat16* Al = g_wl + (size_t)mat * KS * D * D;
    const __nv_bfloat16* Xh = g_xh + (size_t)b * N * D;
    const __nv_bfloat16* Xl = g_xl + (size_t)b * N * D;

    float acc[4][4][4];
#pragma unroll
    for (int i = 0; i < 4; i++)
#pragma unroll
        for (int j = 0; j < 4; j++)
#pragma unroll
            for (int r = 0; r < 4; r++) acc[i][j][r] = 0.f;

    for (int cc = 0; cc < 4; cc++) {
        int c64 = cc * 64;
        for (int k = 0; k < KS; k++) {
            __syncthreads();
            if (k == 0) {
                for (int ch = t; ch < 1152; ch += 256) {
                    int row = ch >> 3, q = ch & 7;
                    int n = n0 - 7 + row;
                    uint32_t off = (uint32_t)(row * ROWB + q * 16);
                    if (n >= 0 && n < N) {
                        size_t gi = (size_t)n * D + c64 + q * 8;
                        *(uint4*)(sm + S_BH + off) = *(const uint4*)(Xh + gi);
                        *(uint4*)(sm + S_BL + off) = *(const uint4*)(Xl + gi);
                    } else {
                        uint4 z = {0u, 0u, 0u, 0u};
                        *(uint4*)(sm + S_BH + off) = z;
                        *(uint4*)(sm + S_BL + off) = z;
                    }
                }
            }
            for (int ch = t; ch < 1024; ch += 256) {
                int row = ch >> 3, q = ch & 7;
                uint32_t off = (uint32_t)(row * ROWB + q * 16);
                size_t gi = ((size_t)(k * D + o0 + row)) * D + c64 + q * 8;
                *(uint4*)(sm + S_AH + off) = *(const uint4*)(Ah + gi);
                *(uint4*)(sm + S_AL + off) = *(const uint4*)(Al + gi);
            }
            __syncthreads();

#pragma unroll
            for (int kc = 0; kc < 4; kc++) {
                uint32_t bh[4][2], bl[4][2];
                {
                    int brow = warp_n + (lane & 7) + k;
                    uint32_t bb = sbase + (uint32_t)(brow * ROWB + kc * 32 + (lane & 8) * 2);
#pragma unroll
                    for (int nt = 0; nt < 4; nt++) {
                        ldsm_x2(bh[nt], bb + S_BH + nt * 8 * ROWB);
                        ldsm_x2(bl[nt], bb + S_BL + nt * 8 * ROWB);
                    }
                }
                int arow = warp_o + (lane & 15);
                uint32_t ab = sbase + (uint32_t)(arow * ROWB + kc * 32 + ((lane >> 4) << 4));
#pragma unroll
                for (int ot = 0; ot < 4; ot++) {
                    uint32_t ah[4], al[4];
                    ldsm_x4(ah, ab + S_AH + ot * 16 * ROWB);
                    ldsm_x4(al, ab + S_AL + ot * 16 * ROWB);
#pragma unroll
                    for (int nt = 0; nt < 4; nt++) {
                        mma16816(acc[ot][nt], ah, bh[nt]);
                        mma16816(acc[ot][nt], ah, bl[nt]);
                        mma16816(acc[ot][nt], al, bh[nt]);
                    }
                }
            }
        }
    }

    const float* bias = (mat == 0) ? bq : (mat == 1) ? bk : bv;
    int g = lane >> 2, cpair = (lane & 3) * 2;
    if (mat < 2) {
        // q/k: write bf16 hi/lo in [b][n][c] (transposed scatter)
        __nv_bfloat16* oh = (mat == 0) ? g_qh : g_kh;
        __nv_bfloat16* ol = (mat == 0) ? g_ql : g_kl;
#pragma unroll
        for (int ot = 0; ot < 4; ot++) {
            int o_lo = o0 + warp_o + ot * 16 + g;
            float bv0 = bias[o_lo], bv1 = bias[o_lo + 8];
#pragma unroll
            for (int nt = 0; nt < 4; nt++) {
                int ncol = n0 + warp_n + nt * 8 + cpair;
                float vals[4] = {acc[ot][nt][0] + bv0, acc[ot][nt][1] + bv0,
                                 acc[ot][nt][2] + bv1, acc[ot][nt][3] + bv1};
                int on[4] = {o_lo, o_lo, o_lo + 8, o_lo + 8};
                int nn[4] = {ncol, ncol + 1, ncol, ncol + 1};
#pragma unroll
                for (int r = 0; r < 4; r++) {
                    size_t gi = ((size_t)(b * N + nn[r])) * D + on[r];
                    __nv_bfloat16 h, l;
                    split_bf16(vals[r], h, l);
                    oh[gi] = h; ol[gi] = l;
                }
            }
        }
    } else {
        // v: write bf16 hi/lo in [b][c][n]
#pragma unroll
        for (int ot = 0; ot < 4; ot++) {
            int o_lo = o0 + warp_o + ot * 16 + g;
            float bv0 = bias[o_lo], bv1 = bias[o_lo + 8];
#pragma unroll
            for (int nt = 0; nt < 4; nt++) {
                int ncol = n0 + warp_n + nt * 8 + cpair;
                __nv_bfloat16 h0, l0, h1, l1;
                size_t gi0 = (size_t)(b * D + o_lo) * N + ncol;
                size_t gi1 = (size_t)(b * D + o_lo + 8) * N + ncol;
                split_bf16(acc[ot][nt][0] + bv0, h0, l0);
                split_bf16(acc[ot][nt][1] + bv0, h1, l1);
                *(__nv_bfloat162*)&g_vh[gi0] = __nv_bfloat162{h0, h1};
                *(__nv_bfloat162*)&g_vl[gi0] = __nv_bfloat162{l0, l1};
                split_bf16(acc[ot][nt][2] + bv1, h0, l0);
                split_bf16(acc[ot][nt][3] + bv1, h1, l1);
                *(__nv_bfloat162*)&g_vh[gi1] = __nv_bfloat162{h0, h1};
                *(__nv_bfloat162*)&g_vl[gi1] = __nv_bfloat162{l0, l1};
            }
        }
    }
}

// ---------------- shared GEMM machinery: D[i][j] = sum_k A[i][k]*B[j][k] ----------------
#define GS_AH 0
#define GS_AL 18432
#define GS_BH 36864
#define GS_BL 55296
#define GEMM_SMEM 73728

__device__ __forceinline__ void load_tile64(char* sm, int soff,
                                            const __nv_bfloat16* gh, const __nv_bfloat16* gl,
                                            int soff_l, size_t rowstride, int t) {
#pragma unroll
    for (int r = 0; r < 4; r++) {
        int ch = t + r * 256;
        int row = ch >> 3, q = ch & 7;
        uint32_t off = (uint32_t)(row * ROWB + q * 16);
        size_t gi = (size_t)row * rowstride + q * 8;
        *(uint4*)(sm + soff + off)   = *(const uint4*)(gh + gi);
        *(uint4*)(sm + soff_l + off) = *(const uint4*)(gl + gi);
    }
}

__device__ __forceinline__ void gemm_chunk(uint32_t sbase, int warp_i, int warp_j,
                                           int lane, float acc[4][4][4]) {
#pragma unroll
    for (int kc = 0; kc < 4; kc++) {
        uint32_t bh[4][2], bl[4][2];
        {
            int brow = warp_j + (lane & 7);
            uint32_t bb = sbase + (uint32_t)(brow * ROWB + kc * 32 + (lane & 8) * 2);
#pragma unroll
            for (int nt = 0; nt < 4; nt++) {
                ldsm_x2(bh[nt], bb + GS_BH + nt * 8 * ROWB);
                ldsm_x2(bl[nt], bb + GS_BL + nt * 8 * ROWB);
            }
        }
        int arow = warp_i + (lane & 15);
        uint32_t ab = sbase + (uint32_t)(arow * ROWB + kc * 32 + ((lane >> 4) << 4));
#pragma unroll
        for (int ot = 0; ot < 4; ot++) {
            uint32_t ah[4], al[4];
            ldsm_x4(ah, ab + GS_AH + ot * 16 * ROWB);
            ldsm_x4(al, ab + GS_AL + ot * 16 * ROWB);
#pragma unroll
            for (int nt = 0; nt < 4; nt++) {
                mma16816(acc[ot][nt], ah, bh[nt]);
                mma16816(acc[ot][nt], ah, bl[nt]);
                mma16816(acc[ot][nt], al, bh[nt]);
            }
        }
    }
}

// ---------------- scores: S[n][m] = (q.k)*scale - dis, masked ----------------
__global__ __launch_bounds__(256) void scores_mma_kernel(const float* __restrict__ dis,
                                                         const int* __restrict__ adj) {
    extern __shared__ char sm[];
    const uint32_t sbase = smem_u32(sm);
    const int t = threadIdx.x, lane = t & 31, wid = t >> 5;
    const int m0 = blockIdx.x * 128;
    const int n0 = blockIdx.y * 128;
    const int b  = blockIdx.z;
    const int warp_n = (wid & 1) * 64;
    const int warp_m = (wid >> 1) * 32;

    float acc[4][4][4];
#pragma unroll
    for (int i = 0; i < 4; i++)
#pragma unroll
        for (int j = 0; j < 4; j++)
#pragma unroll
            for (int r = 0; r < 4; r++) acc[i][j][r] = 0.f;

    for (int cc = 0; cc < 4; cc++) {
        int c64 = cc * 64;
        __syncthreads();
        load_tile64(sm, GS_AH, g_qh + (size_t)(b * N + n0) * D + c64,
                    g_ql + (size_t)(b * N + n0) * D + c64, GS_AL, D, t);
        load_tile64(sm, GS_BH, g_kh + (size_t)(b * N + m0) * D + c64,
                    g_kl + (size_t)(b * N + m0) * D + c64, GS_BL, D, t);
        __syncthreads();
        gemm_chunk(sbase, warp_n, warp_m, lane, acc);
    }

    const float scale = 0.0625f;
    int g = lane >> 2, cpair = (lane & 3) * 2;
#pragma unroll
    for (int ot = 0; ot < 4; ot++) {
#pragma unroll
        for (int half = 0; half < 2; half++) {
            int n = n0 + warp_n + ot * 16 + g + half * 8;
#pragma unroll
            for (int nt = 0; nt < 4; nt++) {
                int m = m0 + warp_m + nt * 8 + cpair;
                size_t base = ((size_t)b * N + n) * N + m;
                float2 d2 = *(const float2*)&dis[base];
                int2   a2 = *(const int2*)&adj[base];
                float s0 = acc[ot][nt][half * 2 + 0] * scale - d2.x;
                float s1 = acc[ot][nt][half * 2 + 1] * scale - d2.y;
                float2 o;
                o.x = (a2.x > 0) ? s0 : -1e9f;
                o.y = (a2.y > 0) ? s1 : -1e9f;
                *(float2*)&g_S[base] = o;
            }
        }
    }
}

// ---------------- softmax: attn bf16 hi/lo + fp32 (xlst+attn) ----------------
__global__ __launch_bounds__(256) void softmax_kernel(const float* __restrict__ xlst,
                                                      float* __restrict__ out_attn) {
    __shared__ float row[N];
    __shared__ float red[256];
    int r = blockIdx.x;
    int t = threadIdx.x;
    size_t base = (size_t)r * N;

    float lmax = -1e30f;
    for (int j = t; j < N; j += 256) { float v = g_S[base + j]; row[j] = v; lmax = fmaxf(lmax, v); }
    red[t] = lmax; __syncthreads();
    for (int s = 128; s > 0; s >>= 1) { if (t < s) red[t] = fmaxf(red[t], red[t + s]); __syncthreads(); }
    float mx = red[0];
    __syncthreads();

    float lsum = 0.f;
    for (int j = t; j < N; j += 256) { float e = __expf(row[j] - mx); row[j] = e; lsum += e; }
    red[t] = lsum; __syncthreads();
    for (int s = 128; s > 0; s >>= 1) { if (t < s) red[t] += red[t + s]; __syncthreads(); }
    float inv = 1.f / red[0];

    for (int j = t; j < N; j += 256) {
        float a = row[j] * inv;
        __nv_bfloat16 h, l;
        split_bf16(a, h, l);
        g_ah[base + j] = h;
        g_al[base + j] = l;
        out_attn[base + j] = xlst[base + j] + a;
    }
}

// ---------------- av: x1[n][c] = sum_m attn[n][m] * v[c][m] ----------------
__global__ __launch_bounds__(256) void av_mma_kernel() {
    extern __shared__ char sm[];
    const uint32_t sbase = smem_u32(sm);
    const int t = threadIdx.x, lane = t & 31, wid = t >> 5;
    const int c0 = blockIdx.x * 128;
    const int n0 = blockIdx.y * 128;
    const int b  = blockIdx.z;
    const int warp_n = (wid & 1) * 64;
    const int warp_c = (wid >> 1) * 32;

    float acc[4][4][4];
#pragma unroll
    for (int i = 0; i < 4; i++)
#pragma unroll
        for (int j = 0; j < 4; j++)
#pragma unroll
            for (int r = 0; r < 4; r++) acc[i][j][r] = 0.f;

    for (int mm = 0; mm < N; mm += 64) {
        __syncthreads();
        load_tile64(sm, GS_AH, g_ah + ((size_t)b * N + n0) * N + mm,
                    g_al + ((size_t)b * N + n0) * N + mm, GS_AL, N, t);
        load_tile64(sm, GS_BH, g_vh + (size_t)(b * D + c0) * N + mm,
                    g_vl + (size_t)(b * D + c0) * N + mm, GS_BL, N, t);
        __syncthreads();
        gemm_chunk(sbase, warp_n, warp_c, lane, acc);
    }

    int g = lane >> 2, cpair = (lane & 3) * 2;
#pragma unroll
    for (int ot = 0; ot < 4; ot++) {
#pragma unroll
        for (int half = 0; half < 2; half++) {
            int n = n0 + warp_n + ot * 16 + g + half * 8;
#pragma unroll
            for (int nt = 0; nt < 4; nt++) {
                int c = c0 + warp_c + nt * 8 + cpair;
                float2 o = {acc[ot][nt][half * 2 + 0], acc[ot][nt][half * 2 + 1]};
                *(float2*)&g_x1[((size_t)(b * N + n)) * D + c] = o;
            }
        }
    }
}

// ---------------- LN: out = LayerNorm(A + Bsrc)*g + be (+ optional bf16 split) ----------------
__global__ __launch_bounds__(256) void add_ln_kernel(const float* __restrict__ A,
                                                     const float* __restrict__ Bsrc,
                                                     const float* __restrict__ g,
                                                     const float* __restrict__ be,
                                                     float* __restrict__ outp,
                                                     int emit_bf16) {
    __shared__ float red[256];
    int r = blockIdx.x, t = threadIdx.x;
    size_t base = (size_t)r * D;
    float x = A[base + t] + Bsrc[base + t];
    red[t] = x; __syncthreads();
    for (int s = 128; s > 0; s >>= 1) { if (t < s) red[t] += red[t + s]; __syncthreads(); }
    float mu = red[0] * (1.f / D);
    __syncthreads();
    float dv = x - mu;
    red[t] = dv * dv; __syncthreads();
    for (int s = 128; s > 0; s >>= 1) { if (t < s) red[t] += red[t + s]; __syncthreads(); }
    float var = red[0] * (1.f / D);
    float y = dv * rsqrtf(var + 1e-5f) * g[t] + be[t];
    outp[base + t] = y;
    if (emit_bf16) {
        __nv_bfloat16 h, l;
        split_bf16(y, h, l);
        g_hh[base + t] = h;
        g_hl[base + t] = l;
    }
}

// ---------------- MLP layer: Y[r][o] = act(X @ W^T + b) ----------------
// mode: 0 = leaky, write bf16 hi/lo; 1 = linear, write fp32
__global__ __launch_bounds__(256) void mlp_mma_kernel(const __nv_bfloat16* __restrict__ Xh,
                                                      const __nv_bfloat16* __restrict__ Xl,
                                                      const __nv_bfloat16* __restrict__ Wh,
                                                      const __nv_bfloat16* __restrict__ Wl,
                                                      const float* __restrict__ bias,
                                                      __nv_bfloat16* __restrict__ Yh,
                                                      __nv_bfloat16* __restrict__ Yl,
                                                      float* __restrict__ Yf,
                                                      int mode) {
    extern __shared__ char sm[];
    const uint32_t sbase = smem_u32(sm);
    const int t = threadIdx.x, lane = t & 31, wid = t >> 5;
    const int o0 = blockIdx.x * 128;
    const int r0 = blockIdx.y * 128;
    const int warp_r = (wid & 1) * 64;
    const int warp_o = (wid >> 1) * 32;

    float acc[4][4][4];
#pragma unroll
    for (int i = 0; i < 4; i++)
#pragma unroll
        for (int j = 0; j < 4; j++)
#pragma unroll
            for (int r = 0; r < 4; r++) acc[i][j][r] = 0.f;

    for (int cc = 0; cc < 4; cc++) {
        int c64 = cc * 64;
        __syncthreads();
        load_tile64(sm, GS_AH, Xh + (size_t)r0 * D + c64, Xl + (size_t)r0 * D + c64, GS_AL, D, t);
        load_tile64(sm, GS_BH, Wh + (size_t)o0 * D + c64, Wl + (size_t)o0 * D + c64, GS_BL, D, t);
        __syncthreads();
        gemm_chunk(sbase, warp_r, warp_o, lane, acc);
    }

    int g = lane >> 2, cpair = (lane & 3) * 2;
#pragma unroll
    for (int ot = 0; ot < 4; ot++) {
#pragma unroll
        for (int half = 0; half < 2; half++) {
            int rr = r0 + warp_r + ot * 16 + g + half * 8;
#pragma unroll
            for (int nt = 0; nt < 4; nt++) {
                int o = o0 + warp_o + nt * 8 + cpair;
                float s0 = acc[ot][nt][half * 2 + 0] + bias[o];
                float s1 = acc[ot][nt][half * 2 + 1] + bias[o + 1];
                if (mode == 0) {
                    s0 = (s0 > 0.f) ? s0 : 0.01f * s0;
                    s1 = (s1 > 0.f) ? s1 : 0.01f * s1;
                    __nv_bfloat16 h0, l0, h1, l1;
                    split_bf16(s0, h0, l0);
                    split_bf16(s1, h1, l1);
                    size_t gi = (size_t)rr * D + o;
                    *(__nv_bfloat162*)&Yh[gi] = __nv_bfloat162{h0, h1};
                    *(__nv_bfloat162*)&Yl[gi] = __nv_bfloat162{l0, l1};
                } else {
                    float2 y = {s0, s1};
                    *(float2*)&Yf[(size_t)rr * D + o] = y;
                }
            }
        }
    }
}

// ---------------- launch ----------------
extern "C" void kernel_launch(void* const* d_in, const int* in_sizes, int n_in,
                              void* d_out, int out_size) {
    const float* src  = (const float*)d_in[0];
    const float* xlst = (const float*)d_in[1];
    const int*   adj  = (const int*)  d_in[2];
    const float* dis  = (const float*)d_in[3];
    const float* Wq = (const float*)d_in[4];
    const float* bq = (const float*)d_in[5];
    const float* Wk = (const float*)d_in[6];
    const float* bk = (const float*)d_in[7];
    const float* Wv = (const float*)d_in[8];
    const float* bv = (const float*)d_in[9];
    const float* W1 = (const float*)d_in[10];
    const float* b1 = (const float*)d_in[11];
    const float* W2 = (const float*)d_in[12];
    const float* b2 = (const float*)d_in[13];
    const float* W3 = (const float*)d_in[14];
    const float* b3 = (const float*)d_in[15];
    const float* g1 = (const float*)d_in[16];
    const float* be1= (const float*)d_in[17];
    const float* g2 = (const float*)d_in[18];
    const float* be2= (const float*)d_in[19];

    float* out_h    = (float*)d_out;
    float* out_attn = out_h + (size_t)B * N * D;

    void *p_x1 = nullptr, *p_h = nullptr;
    cudaGetSymbolAddress(&p_x1, g_x1);
    cudaGetSymbolAddress(&p_h,  g_h);
    float* x1 = (float*)p_x1;
    float* h  = (float*)p_h;

    void *p_hh, *p_hl, *p_m1h, *p_m1l, *p_m2h, *p_m2l, *p_wh, *p_wl;
    cudaGetSymbolAddress(&p_hh, g_hh);   cudaGetSymbolAddress(&p_hl, g_hl);
    cudaGetSymbolAddress(&p_m1h, g_m1h); cudaGetSymbolAddress(&p_m1l, g_m1l);
    cudaGetSymbolAddress(&p_m2h, g_m2h); cudaGetSymbolAddress(&p_m2l, g_m2l);
    cudaGetSymbolAddress(&p_wh, g_w123h); cudaGetSymbolAddress(&p_wl, g_w123l);
    __nv_bfloat16* hh = (__nv_bfloat16*)p_hh;
    __nv_bfloat16* hl = (__nv_bfloat16*)p_hl;
    __nv_bfloat16* m1h = (__nv_bfloat16*)p_m1h;
    __nv_bfloat16* m1l = (__nv_bfloat16*)p_m1l;
    __nv_bfloat16* m2h = (__nv_bfloat16*)p_m2h;
    __nv_bfloat16* m2l = (__nv_bfloat16*)p_m2l;
    __nv_bfloat16* wh = (__nv_bfloat16*)p_wh;
    __nv_bfloat16* wl = (__nv_bfloat16*)p_wl;

    cudaFuncSetAttribute(conv_mma_kernel, cudaFuncAttributeMaxDynamicSharedMemorySize, CONV_SMEM);
    cudaFuncSetAttribute(scores_mma_kernel, cudaFuncAttributeMaxDynamicSharedMemorySize, GEMM_SMEM);
    cudaFuncSetAttribute(av_mma_kernel, cudaFuncAttributeMaxDynamicSharedMemorySize, GEMM_SMEM);
    cudaFuncSetAttribute(mlp_mma_kernel, cudaFuncAttributeMaxDynamicSharedMemorySize, GEMM_SMEM);

    prep_x_kernel  <<<(B * N * D) / 256, 256>>>(src);
    prep_w_kernel  <<<dim3((KS * D * D) / 256, 3), 256>>>(Wq, Wk, Wv);
    prep_w2_kernel <<<dim3((D * D) / 256, 3), 256>>>(W1, W2, W3);
    conv_mma_kernel<<<dim3(N / 128, 2, 12), 256, CONV_SMEM>>>(bq, bk, bv);
    scores_mma_kernel<<<dim3(N / 128, N / 128, B), 256, GEMM_SMEM>>>(dis, adj);
    softmax_kernel <<<B * N, 256>>>(xlst, out_attn);
    av_mma_kernel  <<<dim3(D / 128, N / 128, B), 256, GEMM_SMEM>>>();
    add_ln_kernel  <<<B * N, 256>>>(src, x1, g1, be1, h, 1);
    mlp_mma_kernel <<<dim3(D / 128, (B * N) / 128), 256, GEMM_SMEM>>>(hh,  hl,  wh,             wl,             b1, m1h, m1l, nullptr, 0);
    mlp_mma_kernel <<<dim3(D / 128, (B * N) / 128), 256, GEMM_SMEM>>>(m1h, m1l, wh + D * D,     wl + D * D,     b2, m2h, m2l, nullptr, 0);
    mlp_mma_kernel <<<dim3(D / 128, (B * N) / 128), 256, GEMM_SMEM>>>(m2h, m2l, wh + 2 * D * D, wl + 2 * D * D, b3, nullptr, nullptr, x1, 1);
    add_ln_kernel  <<<B * N, 256>>>(h, x1, g2, be2, out_h, 0);
}

// round 6
// speedup vs baseline: 3.6596x; 1.2297x over previous
#include <cuda_runtime.h>
#include <cuda_bf16.h>
#include <math.h>
#include <stdint.h>

#define B 4
#define N 2048
#define D 256
#define KS 16

typedef unsigned long long u64;

// ---------------- scratch (device globals: allocation-free) ----------------
__device__ float g_S [(size_t)B * N * N]; // masked scores (softmax input)
__device__ float g_x1[B * N * D];         // attn@v result; reused for m3
__device__ float g_h [B * N * D];
// conv inputs (bf16 split)
__device__ __align__(16) __nv_bfloat16 g_xh[B * N * D];
__device__ __align__(16) __nv_bfloat16 g_xl[B * N * D];
__device__ __align__(16) __nv_bfloat16 g_wh[3 * KS * D * D]; // [mat][k][o][c]
__device__ __align__(16) __nv_bfloat16 g_wl[3 * KS * D * D];
// conv outputs (bf16 split)
__device__ __align__(16) __nv_bfloat16 g_qh[B * N * D];  // [b][n][c]
__device__ __align__(16) __nv_bfloat16 g_ql[B * N * D];
__device__ __align__(16) __nv_bfloat16 g_kh[B * N * D];  // [b][n][c]
__device__ __align__(16) __nv_bfloat16 g_kl[B * N * D];
__device__ __align__(16) __nv_bfloat16 g_vh[B * D * N];  // [b][c][n]
__device__ __align__(16) __nv_bfloat16 g_vl[B * D * N];
// attn (bf16 split)
__device__ __align__(16) __nv_bfloat16 g_ah[(size_t)B * N * N];
__device__ __align__(16) __nv_bfloat16 g_al[(size_t)B * N * N];
// MLP activations (bf16 split) + weights
__device__ __align__(16) __nv_bfloat16 g_hh[B * N * D];
__device__ __align__(16) __nv_bfloat16 g_hl[B * N * D];
__device__ __align__(16) __nv_bfloat16 g_m1h[B * N * D];
__device__ __align__(16) __nv_bfloat16 g_m1l[B * N * D];
__device__ __align__(16) __nv_bfloat16 g_m2h[B * N * D];
__device__ __align__(16) __nv_bfloat16 g_m2l[B * N * D];
__device__ __align__(16) __nv_bfloat16 g_w123h[3 * D * D];
__device__ __align__(16) __nv_bfloat16 g_w123l[3 * D * D];

// ---------------- generic-PTX helpers ----------------
__device__ __forceinline__ uint32_t smem_u32(const void* p) {
    uint32_t a;
    asm("{ .reg .u64 t; cvta.to.shared.u64 t, %1; cvt.u32.u64 %0, t; }" : "=r"(a) : "l"(p));
    return a;
}
__device__ __forceinline__ void ldsm_x4(uint32_t* r, uint32_t addr) {
    asm volatile("ldmatrix.sync.aligned.m8n8.x4.shared.b16 {%0,%1,%2,%3}, [%4];"
                 : "=r"(r[0]), "=r"(r[1]), "=r"(r[2]), "=r"(r[3]) : "r"(addr));
}
__device__ __forceinline__ void ldsm_x2(uint32_t* r, uint32_t addr) {
    asm volatile("ldmatrix.sync.aligned.m8n8.x2.shared.b16 {%0,%1}, [%2];"
                 : "=r"(r[0]), "=r"(r[1]) : "r"(addr));
}
__device__ __forceinline__ void mma16816(float* d, const uint32_t* a, const uint32_t* b) {
    asm volatile(
        "mma.sync.aligned.m16n8k16.row.col.f32.bf16.bf16.f32 "
        "{%0,%1,%2,%3}, {%4,%5,%6,%7}, {%8,%9}, {%0,%1,%2,%3};"
        : "+f"(d[0]), "+f"(d[1]), "+f"(d[2]), "+f"(d[3])
        : "r"(a[0]), "r"(a[1]), "r"(a[2]), "r"(a[3]), "r"(b[0]), "r"(b[1]));
}
__device__ __forceinline__ void split_bf16(float f, __nv_bfloat16& h, __nv_bfloat16& l) {
    h = __float2bfloat16_rn(f);
    l = __float2bfloat16_rn(f - __bfloat162float(h));
}
__device__ __forceinline__ void cp16(uint32_t dst, const void* src) {
    asm volatile("cp.async.cg.shared.global [%0], [%1], 16;" :: "r"(dst), "l"(src));
}
__device__ __forceinline__ void cp_commit() { asm volatile("cp.async.commit_group;" ::: "memory"); }
__device__ __forceinline__ void cp_wait0() { asm volatile("cp.async.wait_group 0;" ::: "memory"); }
__device__ __forceinline__ void cp_wait1() { asm volatile("cp.async.wait_group 1;" ::: "memory"); }

// ---------------- prep kernels ----------------
__global__ __launch_bounds__(256) void prep_x_kernel(const float* __restrict__ src) {
    int i = blockIdx.x * 256 + threadIdx.x;
    split_bf16(src[i], g_xh[i], g_xl[i]);
}
__global__ __launch_bounds__(256) void prep_w_kernel(const float* __restrict__ Wq,
                                                     const float* __restrict__ Wk,
                                                     const float* __restrict__ Wv) {
    int i = blockIdx.x * 256 + threadIdx.x;   // [k][o][c]
    int mat = blockIdx.y;
    const float* W = (mat == 0) ? Wq : (mat == 1) ? Wk : Wv;
    int c = i & 255, o = (i >> 8) & 255, k = i >> 16;
    float f = W[((size_t)(o * D + c)) * KS + k];
    size_t oi = (size_t)mat * KS * D * D + i;
    split_bf16(f, g_wh[oi], g_wl[oi]);
}
__global__ __launch_bounds__(256) void prep_w2_kernel(const float* __restrict__ W1,
                                                      const float* __restrict__ W2,
                                                      const float* __restrict__ W3) {
    int i = blockIdx.x * 256 + threadIdx.x;   // [o][c]
    int mat = blockIdx.y;
    const float* W = (mat == 0) ? W1 : (mat == 1) ? W2 : W3;
    size_t oi = (size_t)mat * D * D + i;
    split_bf16(W[i], g_w123h[oi], g_w123l[oi]);
}

#define ROWB 144

// ---------------- HMMA conv (double-buffered A via cp.async) ----------------
// smem: A bufs {0, 36864} (hi, lo at +18432); B at 73728 (hi), 94464 (lo)
#define C_BH 73728
#define C_BL 94464
#define CONV_SMEM 115200

__global__ __launch_bounds__(256) void conv_mma_kernel(const float* __restrict__ bq,
                                                       const float* __restrict__ bk,
                                                       const float* __restrict__ bv) {
    extern __shared__ char sm[];
    const uint32_t sbase = smem_u32(sm);
    const int t = threadIdx.x;
    const int lane = t & 31, wid = t >> 5;
    const int n0 = blockIdx.x * 128;
    const int o0 = blockIdx.y * 128;
    const int mat = blockIdx.z >> 2;
    const int b   = blockIdx.z & 3;
    const int warp_o = (wid & 1) * 64;
    const int warp_n = (wid >> 1) * 32;

    const __nv_bfloat16* Ah = g_wh + (size_t)mat * KS * D * D;
    const __nv_bfloat16* Al = g_wl + (size_t)mat * KS * D * D;
    const __nv_bfloat16* Xh = g_xh + (size_t)b * N * D;
    const __nv_bfloat16* Xl = g_xl + (size_t)b * N * D;

    float acc[4][4][4];
#pragma unroll
    for (int i = 0; i < 4; i++)
#pragma unroll
        for (int j = 0; j < 4; j++)
#pragma unroll
            for (int r = 0; r < 4; r++) acc[i][j][r] = 0.f;

    const uint32_t abufs[2] = {sbase, sbase + 36864};

    // loaders
    auto loadA = [&](int it, int buf) {
        int k = it & 15, cc = it >> 4;
#pragma unroll
        for (int r = 0; r < 4; r++) {
            int ch = t + r * 256;
            int row = ch >> 3, q = ch & 7;
            uint32_t off = (uint32_t)(row * ROWB + q * 16);
            size_t gi = ((size_t)(k * D + o0 + row)) * D + cc * 64 + q * 8;
            cp16(abufs[buf] + off, Ah + gi);
            cp16(abufs[buf] + 18432 + off, Al + gi);
        }
    };
    auto loadB = [&](int cc) {
        for (int ch = t; ch < 1152; ch += 256) {
            int row = ch >> 3, q = ch & 7;
            int n = n0 - 7 + row;
            uint32_t off = (uint32_t)(row * ROWB + q * 16);
            if (n >= 0 && n < N) {
                size_t gi = (size_t)n * D + cc * 64 + q * 8;
                cp16(sbase + C_BH + off, Xh + gi);
                cp16(sbase + C_BL + off, Xl + gi);
            } else {
                uint4 z = {0u, 0u, 0u, 0u};
                *(uint4*)(sm + C_BH + off) = z;
                *(uint4*)(sm + C_BL + off) = z;
            }
        }
    };

    loadB(0);
    loadA(0, 0);
    cp_commit();
    cp_wait0();
    __syncthreads();

    int p = 0;
    for (int it = 0; it < 64; it++) {
        if (it + 1 < 64) { loadA(it + 1, p ^ 1); cp_commit(); }

        const int k = it & 15;
        const uint32_t ab0 = abufs[p];
#pragma unroll
        for (int kc = 0; kc < 4; kc++) {
            uint32_t bh[4][2], bl[4][2];
            {
                int brow = warp_n + (lane & 7) + k;
                uint32_t bb = sbase + (uint32_t)(brow * ROWB + kc * 32 + (lane & 8) * 2);
#pragma unroll
                for (int nt = 0; nt < 4; nt++) {
                    ldsm_x2(bh[nt], bb + C_BH + nt * 8 * ROWB);
                    ldsm_x2(bl[nt], bb + C_BL + nt * 8 * ROWB);
                }
            }
            int arow = warp_o + (lane & 15);
            uint32_t ab = ab0 + (uint32_t)(arow * ROWB + kc * 32 + ((lane >> 4) << 4));
#pragma unroll
            for (int ot = 0; ot < 4; ot++) {
                uint32_t ah[4], al[4];
                ldsm_x4(ah, ab + ot * 16 * ROWB);
                ldsm_x4(al, ab + 18432 + ot * 16 * ROWB);
#pragma unroll
                for (int nt = 0; nt < 4; nt++) {
                    mma16816(acc[ot][nt], ah, bh[nt]);
                    mma16816(acc[ot][nt], ah, bl[nt]);
                    mma16816(acc[ot][nt], al, bh[nt]);
                }
            }
        }
        __syncthreads();
        if (it + 1 < 64) {
            if (((it + 1) & 15) == 0) { loadB((it + 1) >> 4); cp_commit(); }
            cp_wait0();
            __syncthreads();
        }
        p ^= 1;
    }

    const float* bias = (mat == 0) ? bq : (mat == 1) ? bk : bv;
    int g = lane >> 2, cpair = (lane & 3) * 2;
    if (mat < 2) {
        __nv_bfloat16* oh = (mat == 0) ? g_qh : g_kh;
        __nv_bfloat16* ol = (mat == 0) ? g_ql : g_kl;
#pragma unroll
        for (int ot = 0; ot < 4; ot++) {
            int o_lo = o0 + warp_o + ot * 16 + g;
            float bv0 = bias[o_lo], bv1 = bias[o_lo + 8];
#pragma unroll
            for (int nt = 0; nt < 4; nt++) {
                int ncol = n0 + warp_n + nt * 8 + cpair;
                float vals[4] = {acc[ot][nt][0] + bv0, acc[ot][nt][1] + bv0,
                                 acc[ot][nt][2] + bv1, acc[ot][nt][3] + bv1};
                int on[4] = {o_lo, o_lo, o_lo + 8, o_lo + 8};
                int nn[4] = {ncol, ncol + 1, ncol, ncol + 1};
#pragma unroll
                for (int r = 0; r < 4; r++) {
                    size_t gi = ((size_t)(b * N + nn[r])) * D + on[r];
                    __nv_bfloat16 h, l;
                    split_bf16(vals[r], h, l);
                    oh[gi] = h; ol[gi] = l;
                }
            }
        }
    } else {
#pragma unroll
        for (int ot = 0; ot < 4; ot++) {
            int o_lo = o0 + warp_o + ot * 16 + g;
            float bv0 = bias[o_lo], bv1 = bias[o_lo + 8];
#pragma unroll
            for (int nt = 0; nt < 4; nt++) {
                int ncol = n0 + warp_n + nt * 8 + cpair;
                __nv_bfloat16 h0, l0, h1, l1;
                size_t gi0 = (size_t)(b * D + o_lo) * N + ncol;
                size_t gi1 = (size_t)(b * D + o_lo + 8) * N + ncol;
                split_bf16(acc[ot][nt][0] + bv0, h0, l0);
                split_bf16(acc[ot][nt][1] + bv0, h1, l1);
                *(__nv_bfloat162*)&g_vh[gi0] = __nv_bfloat162{h0, h1};
                *(__nv_bfloat162*)&g_vl[gi0] = __nv_bfloat162{l0, l1};
                split_bf16(acc[ot][nt][2] + bv1, h0, l0);
                split_bf16(acc[ot][nt][3] + bv1, h1, l1);
                *(__nv_bfloat162*)&g_vh[gi1] = __nv_bfloat162{h0, h1};
                *(__nv_bfloat162*)&g_vl[gi1] = __nv_bfloat162{l0, l1};
            }
        }
    }
}

// ---------------- shared double-buffered GEMM machinery ----------------
// buffer layout (relative to buffer base): AH 0, AL 18432, BH 36864, BL 55296
#define GBUF 73728
#define GEMM_SMEM 147456

__device__ __forceinline__ void load_AB_cp(uint32_t buf,
                                           const __nv_bfloat16* Ahp, const __nv_bfloat16* Alp,
                                           size_t strideA,
                                           const __nv_bfloat16* Bhp, const __nv_bfloat16* Blp,
                                           size_t strideB, int t) {
#pragma unroll
    for (int r = 0; r < 4; r++) {
        int ch = t + r * 256;
        int row = ch >> 3, q = ch & 7;
        uint32_t off = (uint32_t)(row * ROWB + q * 16);
        cp16(buf + off,         Ahp + (size_t)row * strideA + q * 8);
        cp16(buf + 18432 + off, Alp + (size_t)row * strideA + q * 8);
        cp16(buf + 36864 + off, Bhp + (size_t)row * strideB + q * 8);
        cp16(buf + 55296 + off, Blp + (size_t)row * strideB + q * 8);
    }
}

__device__ __forceinline__ void gemm_chunk(uint32_t buf, int warp_i, int warp_j,
                                           int lane, float acc[4][4][4]) {
#pragma unroll
    for (int kc = 0; kc < 4; kc++) {
        uint32_t bh[4][2], bl[4][2];
        {
            int brow = warp_j + (lane & 7);
            uint32_t bb = buf + (uint32_t)(brow * ROWB + kc * 32 + (lane & 8) * 2);
#pragma unroll
            for (int nt = 0; nt < 4; nt++) {
                ldsm_x2(bh[nt], bb + 36864 + nt * 8 * ROWB);
                ldsm_x2(bl[nt], bb + 55296 + nt * 8 * ROWB);
            }
        }
        int arow = warp_i + (lane & 15);
        uint32_t ab = buf + (uint32_t)(arow * ROWB + kc * 32 + ((lane >> 4) << 4));
#pragma unroll
        for (int ot = 0; ot < 4; ot++) {
            uint32_t ah[4], al[4];
            ldsm_x4(ah, ab + ot * 16 * ROWB);
            ldsm_x4(al, ab + 18432 + ot * 16 * ROWB);
#pragma unroll
            for (int nt = 0; nt < 4; nt++) {
                mma16816(acc[ot][nt], ah, bh[nt]);
                mma16816(acc[ot][nt], ah, bl[nt]);
                mma16816(acc[ot][nt], al, bh[nt]);
            }
        }
    }
}

// ---------------- scores ----------------
__global__ __launch_bounds__(256) void scores_mma_kernel(const float* __restrict__ dis,
                                                         const int* __restrict__ adj) {
    extern __shared__ char sm[];
    const uint32_t sbase = smem_u32(sm);
    const int t = threadIdx.x, lane = t & 31, wid = t >> 5;
    const int m0 = blockIdx.x * 128;
    const int n0 = blockIdx.y * 128;
    const int b  = blockIdx.z;
    const int warp_n = (wid & 1) * 64;
    const int warp_m = (wid >> 1) * 32;

    float acc[4][4][4];
#pragma unroll
    for (int i = 0; i < 4; i++)
#pragma unroll
        for (int j = 0; j < 4; j++)
#pragma unroll
            for (int r = 0; r < 4; r++) acc[i][j][r] = 0.f;

    const __nv_bfloat16* Ahp = g_qh + (size_t)(b * N + n0) * D;
    const __nv_bfloat16* Alp = g_ql + (size_t)(b * N + n0) * D;
    const __nv_bfloat16* Bhp = g_kh + (size_t)(b * N + m0) * D;
    const __nv_bfloat16* Blp = g_kl + (size_t)(b * N + m0) * D;
    const uint32_t bufs[2] = {sbase, sbase + GBUF};

    load_AB_cp(bufs[0], Ahp, Alp, D, Bhp, Blp, D, t);
    cp_commit();
    int p = 0;
    for (int i = 0; i < 4; i++) {
        if (i + 1 < 4) {
            load_AB_cp(bufs[p ^ 1], Ahp + (i + 1) * 64, Alp + (i + 1) * 64, D,
                       Bhp + (i + 1) * 64, Blp + (i + 1) * 64, D, t);
            cp_commit();
            cp_wait1();
        } else cp_wait0();
        __syncthreads();
        gemm_chunk(bufs[p], warp_n, warp_m, lane, acc);
        __syncthreads();
        p ^= 1;
    }

    const float scale = 0.0625f;
    int g = lane >> 2, cpair = (lane & 3) * 2;
#pragma unroll
    for (int ot = 0; ot < 4; ot++) {
#pragma unroll
        for (int half = 0; half < 2; half++) {
            int n = n0 + warp_n + ot * 16 + g + half * 8;
#pragma unroll
            for (int nt = 0; nt < 4; nt++) {
                int m = m0 + warp_m + nt * 8 + cpair;
                size_t base = ((size_t)b * N + n) * N + m;
                float2 d2 = *(const float2*)&dis[base];
                int2   a2 = *(const int2*)&adj[base];
                float s0 = acc[ot][nt][half * 2 + 0] * scale - d2.x;
                float s1 = acc[ot][nt][half * 2 + 1] * scale - d2.y;
                float2 o;
                o.x = (a2.x > 0) ? s0 : -1e9f;
                o.y = (a2.y > 0) ? s1 : -1e9f;
                *(float2*)&g_S[base] = o;
            }
        }
    }
}

// ---------------- softmax: register-resident, vectorized ----------------
__global__ __launch_bounds__(256) void softmax_kernel(const float* __restrict__ xlst,
                                                      float* __restrict__ out_attn) {
    __shared__ float red[8];
    int r = blockIdx.x;
    int t = threadIdx.x;
    int lane = t & 31, wid = t >> 5;
    size_t base = (size_t)r * N;
    int j0 = t * 8;

    float4 v0 = *(const float4*)&g_S[base + j0];
    float4 v1 = *(const float4*)&g_S[base + j0 + 4];
    float x[8] = {v0.x, v0.y, v0.z, v0.w, v1.x, v1.y, v1.z, v1.w};

    float lmax = x[0];
#pragma unroll
    for (int i = 1; i < 8; i++) lmax = fmaxf(lmax, x[i]);
#pragma unroll
    for (int off = 16; off > 0; off >>= 1)
        lmax = fmaxf(lmax, __shfl_xor_sync(0xffffffffu, lmax, off));
    if (lane == 0) red[wid] = lmax;
    __syncthreads();
    float mx = red[0];
#pragma unroll
    for (int w = 1; w < 8; w++) mx = fmaxf(mx, red[w]);
    __syncthreads();

    float e[8];
    float lsum = 0.f;
#pragma unroll
    for (int i = 0; i < 8; i++) { e[i] = __expf(x[i] - mx); lsum += e[i]; }
#pragma unroll
    for (int off = 16; off > 0; off >>= 1)
        lsum += __shfl_xor_sync(0xffffffffu, lsum, off);
    if (lane == 0) red[wid] = lsum;
    __syncthreads();
    float tot = 0.f;
#pragma unroll
    for (int w = 0; w < 8; w++) tot += red[w];
    float inv = 1.f / tot;

    union { __nv_bfloat16 b[8]; uint4 u; } hb, lb;
    float4 xl0 = *(const float4*)&xlst[base + j0];
    float4 xl1 = *(const float4*)&xlst[base + j0 + 4];
    float xl[8] = {xl0.x, xl0.y, xl0.z, xl0.w, xl1.x, xl1.y, xl1.z, xl1.w};
    float a[8];
#pragma unroll
    for (int i = 0; i < 8; i++) {
        a[i] = e[i] * inv;
        split_bf16(a[i], hb.b[i], lb.b[i]);
    }
    *(uint4*)&g_ah[base + j0] = hb.u;
    *(uint4*)&g_al[base + j0] = lb.u;
    float4 o0 = {xl[0] + a[0], xl[1] + a[1], xl[2] + a[2], xl[3] + a[3]};
    float4 o1 = {xl[4] + a[4], xl[5] + a[5], xl[6] + a[6], xl[7] + a[7]};
    *(float4*)&out_attn[base + j0] = o0;
    *(float4*)&out_attn[base + j0 + 4] = o1;
}

// ---------------- av ----------------
__global__ __launch_bounds__(256) void av_mma_kernel() {
    extern __shared__ char sm[];
    const uint32_t sbase = smem_u32(sm);
    const int t = threadIdx.x, lane = t & 31, wid = t >> 5;
    const int c0 = blockIdx.x * 128;
    const int n0 = blockIdx.y * 128;
    const int b  = blockIdx.z;
    const int warp_n = (wid & 1) * 64;
    const int warp_c = (wid >> 1) * 32;

    float acc[4][4][4];
#pragma unroll
    for (int i = 0; i < 4; i++)
#pragma unroll
        for (int j = 0; j < 4; j++)
#pragma unroll
            for (int r = 0; r < 4; r++) acc[i][j][r] = 0.f;

    const __nv_bfloat16* Ahp = g_ah + ((size_t)b * N + n0) * N;
    const __nv_bfloat16* Alp = g_al + ((size_t)b * N + n0) * N;
    const __nv_bfloat16* Bhp = g_vh + (size_t)(b * D + c0) * N;
    const __nv_bfloat16* Blp = g_vl + (size_t)(b * D + c0) * N;
    const uint32_t bufs[2] = {sbase, sbase + GBUF};

    load_AB_cp(bufs[0], Ahp, Alp, N, Bhp, Blp, N, t);
    cp_commit();
    int p = 0;
    for (int i = 0; i < 32; i++) {
        if (i + 1 < 32) {
            load_AB_cp(bufs[p ^ 1], Ahp + (i + 1) * 64, Alp + (i + 1) * 64, N,
                       Bhp + (i + 1) * 64, Blp + (i + 1) * 64, N, t);
            cp_commit();
            cp_wait1();
        } else cp_wait0();
        __syncthreads();
        gemm_chunk(bufs[p], warp_n, warp_c, lane, acc);
        __syncthreads();
        p ^= 1;
    }

    int g = lane >> 2, cpair = (lane & 3) * 2;
#pragma unroll
    for (int ot = 0; ot < 4; ot++) {
#pragma unroll
        for (int half = 0; half < 2; half++) {
            int n = n0 + warp_n + ot * 16 + g + half * 8;
#pragma unroll
            for (int nt = 0; nt < 4; nt++) {
                int c = c0 + warp_c + nt * 8 + cpair;
                float2 o = {acc[ot][nt][half * 2 + 0], acc[ot][nt][half * 2 + 1]};
                *(float2*)&g_x1[((size_t)(b * N + n)) * D + c] = o;
            }
        }
    }
}

// ---------------- LN ----------------
__global__ __launch_bounds__(256) void add_ln_kernel(const float* __restrict__ A,
                                                     const float* __restrict__ Bsrc,
                                                     const float* __restrict__ g,
                                                     const float* __restrict__ be,
                                                     float* __restrict__ outp,
                                                     int emit_bf16) {
    __shared__ float red[256];
    int r = blockIdx.x, t = threadIdx.x;
    size_t base = (size_t)r * D;
    float x = A[base + t] + Bsrc[base + t];
    red[t] = x; __syncthreads();
    for (int s = 128; s > 0; s >>= 1) { if (t < s) red[t] += red[t + s]; __syncthreads(); }
    float mu = red[0] * (1.f / D);
    __syncthreads();
    float dv = x - mu;
    red[t] = dv * dv; __syncthreads();
    for (int s = 128; s > 0; s >>= 1) { if (t < s) red[t] += red[t + s]; __syncthreads(); }
    float var = red[0] * (1.f / D);
    float y = dv * rsqrtf(var + 1e-5f) * g[t] + be[t];
    outp[base + t] = y;
    if (emit_bf16) {
        __nv_bfloat16 h, l;
        split_bf16(y, h, l);
        g_hh[base + t] = h;
        g_hl[base + t] = l;
    }
}

// ---------------- MLP ----------------
__global__ __launch_bounds__(256) void mlp_mma_kernel(const __nv_bfloat16* __restrict__ Xh,
                                                      const __nv_bfloat16* __restrict__ Xl,
                                                      const __nv_bfloat16* __restrict__ Wh,
                                                      const __nv_bfloat16* __restrict__ Wl,
                                                      const float* __restrict__ bias,
                                                      __nv_bfloat16* __restrict__ Yh,
                                                      __nv_bfloat16* __restrict__ Yl,
                                                      float* __restrict__ Yf,
                                                      int mode) {
    extern __shared__ char sm[];
    const uint32_t sbase = smem_u32(sm);
    const int t = threadIdx.x, lane = t & 31, wid = t >> 5;
    const int o0 = blockIdx.x * 128;
    const int r0 = blockIdx.y * 128;
    const int warp_r = (wid & 1) * 64;
    const int warp_o = (wid >> 1) * 32;

    float acc[4][4][4];
#pragma unroll
    for (int i = 0; i < 4; i++)
#pragma unroll
        for (int j = 0; j < 4; j++)
#pragma unroll
            for (int r = 0; r < 4; r++) acc[i][j][r] = 0.f;

    const __nv_bfloat16* Ahp = Xh + (size_t)r0 * D;
    const __nv_bfloat16* Alp = Xl + (size_t)r0 * D;
    const __nv_bfloat16* Bhp = Wh + (size_t)o0 * D;
    const __nv_bfloat16* Blp = Wl + (size_t)o0 * D;
    const uint32_t bufs[2] = {sbase, sbase + GBUF};

    load_AB_cp(bufs[0], Ahp, Alp, D, Bhp, Blp, D, t);
    cp_commit();
    int p = 0;
    for (int i = 0; i < 4; i++) {
        if (i + 1 < 4) {
            load_AB_cp(bufs[p ^ 1], Ahp + (i + 1) * 64, Alp + (i + 1) * 64, D,
                       Bhp + (i + 1) * 64, Blp + (i + 1) * 64, D, t);
            cp_commit();
            cp_wait1();
        } else cp_wait0();
        __syncthreads();
        gemm_chunk(bufs[p], warp_r, warp_o, lane, acc);
        __syncthreads();
        p ^= 1;
    }

    int g = lane >> 2, cpair = (lane & 3) * 2;
#pragma unroll
    for (int ot = 0; ot < 4; ot++) {
#pragma unroll
        for (int half = 0; half < 2; half++) {
            int rr = r0 + warp_r + ot * 16 + g + half * 8;
#pragma unroll
            for (int nt = 0; nt < 4; nt++) {
                int o = o0 + warp_o + nt * 8 + cpair;
                float s0 = acc[ot][nt][half * 2 + 0] + bias[o];
                float s1 = acc[ot][nt][half * 2 + 1] + bias[o + 1];
                if (mode == 0) {
                    s0 = (s0 > 0.f) ? s0 : 0.01f * s0;
                    s1 = (s1 > 0.f) ? s1 : 0.01f * s1;
                    __nv_bfloat16 h0, l0, h1, l1;
                    split_bf16(s0, h0, l0);
                    split_bf16(s1, h1, l1);
                    size_t gi = (size_t)rr * D + o;
                    *(__nv_bfloat162*)&Yh[gi] = __nv_bfloat162{h0, h1};
                    *(__nv_bfloat162*)&Yl[gi] = __nv_bfloat162{l0, l1};
                } else {
                    float2 y = {s0, s1};
                    *(float2*)&Yf[(size_t)rr * D + o] = y;
                }
            }
        }
    }
}

// ---------------- launch ----------------
extern "C" void kernel_launch(void* const* d_in, const int* in_sizes, int n_in,
                              void* d_out, int out_size) {
    const float* src  = (const float*)d_in[0];
    const float* xlst = (const float*)d_in[1];
    const int*   adj  = (const int*)  d_in[2];
    const float* dis  = (const float*)d_in[3];
    const float* Wq = (const float*)d_in[4];
    const float* bq = (const float*)d_in[5];
    const float* Wk = (const float*)d_in[6];
    const float* bk = (const float*)d_in[7];
    const float* Wv = (const float*)d_in[8];
    const float* bv = (const float*)d_in[9];
    const float* W1 = (const float*)d_in[10];
    const float* b1 = (const float*)d_in[11];
    const float* W2 = (const float*)d_in[12];
    const float* b2 = (const float*)d_in[13];
    const float* W3 = (const float*)d_in[14];
    const float* b3 = (const float*)d_in[15];
    const float* g1 = (const float*)d_in[16];
    const float* be1= (const float*)d_in[17];
    const float* g2 = (const float*)d_in[18];
    const float* be2= (const float*)d_in[19];

    float* out_h    = (float*)d_out;
    float* out_attn = out_h + (size_t)B * N * D;

    void *p_x1 = nullptr, *p_h = nullptr;
    cudaGetSymbolAddress(&p_x1, g_x1);
    cudaGetSymbolAddress(&p_h,  g_h);
    float* x1 = (float*)p_x1;
    float* h  = (float*)p_h;

    void *p_hh, *p_hl, *p_m1h, *p_m1l, *p_m2h, *p_m2l, *p_wh, *p_wl;
    cudaGetSymbolAddress(&p_hh, g_hh);   cudaGetSymbolAddress(&p_hl, g_hl);
    cudaGetSymbolAddress(&p_m1h, g_m1h); cudaGetSymbolAddress(&p_m1l, g_m1l);
    cudaGetSymbolAddress(&p_m2h, g_m2h); cudaGetSymbolAddress(&p_m2l, g_m2l);
    cudaGetSymbolAddress(&p_wh, g_w123h); cudaGetSymbolAddress(&p_wl, g_w123l);
    __nv_bfloat16* hh = (__nv_bfloat16*)p_hh;
    __nv_bfloat16* hl = (__nv_bfloat16*)p_hl;
    __nv_bfloat16* m1h = (__nv_bfloat16*)p_m1h;
    __nv_bfloat16* m1l = (__nv_bfloat16*)p_m1l;
    __nv_bfloat16* m2h = (__nv_bfloat16*)p_m2h;
    __nv_bfloat16* m2l = (__nv_bfloat16*)p_m2l;
    __nv_bfloat16* wh = (__nv_bfloat16*)p_wh;
    __nv_bfloat16* wl = (__nv_bfloat16*)p_wl;

    cudaFuncSetAttribute(conv_mma_kernel, cudaFuncAttributeMaxDynamicSharedMemorySize, CONV_SMEM);
    cudaFuncSetAttribute(scores_mma_kernel, cudaFuncAttributeMaxDynamicSharedMemorySize, GEMM_SMEM);
    cudaFuncSetAttribute(av_mma_kernel, cudaFuncAttributeMaxDynamicSharedMemorySize, GEMM_SMEM);
    cudaFuncSetAttribute(mlp_mma_kernel, cudaFuncAttributeMaxDynamicSharedMemorySize, GEMM_SMEM);

    prep_x_kernel  <<<(B * N * D) / 256, 256>>>(src);
    prep_w_kernel  <<<dim3((KS * D * D) / 256, 3), 256>>>(Wq, Wk, Wv);
    prep_w2_kernel <<<dim3((D * D) / 256, 3), 256>>>(W1, W2, W3);
    conv_mma_kernel<<<dim3(N / 128, 2, 12), 256, CONV_SMEM>>>(bq, bk, bv);
    scores_mma_kernel<<<dim3(N / 128, N / 128, B), 256, GEMM_SMEM>>>(dis, adj);
    softmax_kernel <<<B * N, 256>>>(xlst, out_attn);
    av_mma_kernel  <<<dim3(D / 128, N / 128, B), 256, GEMM_SMEM>>>();
    add_ln_kernel  <<<B * N, 256>>>(src, x1, g1, be1, h, 1);
    mlp_mma_kernel <<<dim3(D / 128, (B * N) / 128), 256, GEMM_SMEM>>>(hh,  hl,  wh,             wl,             b1, m1h, m1l, nullptr, 0);
    mlp_mma_kernel <<<dim3(D / 128, (B * N) / 128), 256, GEMM_SMEM>>>(m1h, m1l, wh + D * D,     wl + D * D,     b2, m2h, m2l, nullptr, 0);
    mlp_mma_kernel <<<dim3(D / 128, (B * N) / 128), 256, GEMM_SMEM>>>(m2h, m2l, wh + 2 * D * D, wl + 2 * D * D, b3, nullptr, nullptr, x1, 1);
    add_ln_kernel  <<<B * N, 256>>>(h, x1, g2, be2, out_h, 0);
}